// round 13
// baseline (speedup 1.0000x reference)
#include <cuda_runtime.h>
#include <math.h>
#include <stdint.h>

#define HW   400
#define LCH  9
#define BS   2
#define CD   1024
#define CH   256
#define NLB  18
#define TEMP 20.0f

typedef unsigned long long u64;

// ---------------- scratch ----------------
__device__ float g_part [2 * NLB * 8 * HW];                 // partial sums
__device__ int   g_cnt  [2 * NLB];                          // arrival counters (self-reset)
__device__ float g_invn [2 * NLB * HW];
__device__ float g_corr [(size_t)NLB * HW * HW];
__device__ float g_corrI[(size_t)NLB * HW * HW * 2];        // (corr, corrT) interleaved
__device__ float g_buf1I[(size_t)BS * 10 * HW * HW * 2];
__device__ float g_buf2I[(size_t)BS * 10 * HW * HW * 2];
__device__ float g_c4abI[(size_t)BS * HW * HW * 2];
__device__ float g_c4   [BS * HW * HW];
__device__ float g_attn [BS * HW * HW];
__device__ float g_nrm  [2 * BS * HW];
__device__ u64   g_wd1  [9 * 81 * 10];                      // (w,w) dup weights
__device__ u64   g_wd2  [10 * 81 * 10];
__device__ u64   g_wd3  [10 * 81 * 1];

// ---------------- f32x2 helpers ----------------
__device__ __forceinline__ u64 pack2(float x, float y) {
    u64 r;
    asm("mov.b64 %0, {%1, %2};" : "=l"(r) : "f"(x), "f"(y));
    return r;
}
__device__ __forceinline__ void unpack2(u64 v, float& x, float& y) {
    asm("mov.b64 {%0, %1}, %2;" : "=f"(x), "=f"(y) : "l"(v));
}
__device__ __forceinline__ void fma2(u64& d, u64 a, u64 b) {
    asm("fma.rn.f32x2 %0, %1, %2, %0;" : "+l"(d) : "l"(a), "l"(b));
}

// ---------------- prep: full-chip partial sumsq + last-block reduce + weight dup ----------------
__global__ void prep_k(const float* __restrict__ fq, const float* __restrict__ fs,
                       float* __restrict__ part, int* __restrict__ cnt,
                       float* __restrict__ inv,
                       const float* __restrict__ w1, const float* __restrict__ w2,
                       const float* __restrict__ w3,
                       u64* __restrict__ o1, u64* __restrict__ o2, u64* __restrict__ o3) {
    int z = blockIdx.y, lb = blockIdx.x, ch = blockIdx.z;
    int pos = threadIdx.x;
    const float* x = (z ? fs : fq) + ((size_t)lb * CD + ch * 128) * HW + pos;
    float s0 = 0.f, s1 = 0.f, s2 = 0.f, s3 = 0.f;
    #pragma unroll 4
    for (int c = 0; c < 128; c += 4) {
        float v0 = x[(size_t)(c + 0) * HW];
        float v1 = x[(size_t)(c + 1) * HW];
        float v2 = x[(size_t)(c + 2) * HW];
        float v3 = x[(size_t)(c + 3) * HW];
        s0 += v0 * v0; s1 += v1 * v1; s2 += v2 * v2; s3 += v3 * v3;
    }
    part[(((size_t)z * NLB + lb) * 8 + ch) * HW + pos] = (s0 + s1) + (s2 + s3);

    if (z == 0 && lb == 0 && ch == 0) {
        for (int idx = pos; idx < 10 * 81 * 10; idx += 400) {
            if (idx < 9 * 81 * 10) {
                int co = idx % 10, rem = idx / 10;
                int ci = rem / 81, tap = rem % 81;
                float w = w1[((size_t)co * 9 + ci) * 81 + tap];
                o1[idx] = pack2(w, w);
            }
            {
                int co = idx % 10, rem = idx / 10;
                int ci = rem / 81, tap = rem % 81;
                float w = w2[((size_t)co * 10 + ci) * 81 + tap];
                o2[idx] = pack2(w, w);
            }
            if (idx < 10 * 81) {
                float w = w3[idx];
                o3[idx] = pack2(w, w);
            }
        }
    }

    __threadfence();
    __syncthreads();
    __shared__ int lastflag;
    if (pos == 0) lastflag = (atomicAdd(&cnt[z * NLB + lb], 1) == 7) ? 1 : 0;
    __syncthreads();
    if (lastflag) {
        const float* p = part + ((size_t)z * NLB + lb) * 8 * HW + pos;
        float s = 0.f;
        #pragma unroll
        for (int c = 0; c < 8; c++) s += p[c * HW];
        inv[z * NLB * HW + lb * HW + pos] = 1.f / fmaxf(sqrtf(s), 1e-12f);
        if (pos == 0) cnt[z * NLB + lb] = 0;
    }
}

// ---------------- correlation GEMM (TN), FFMA2 + register prefetch (R4 config) ----------------
__global__ void __launch_bounds__(400) corr_gemm_k(
        const float* __restrict__ fq, const float* __restrict__ fs,
        const float* __restrict__ invn, float* __restrict__ corr) {
    int lb = blockIdx.z;
    const float* A  = fq + (size_t)lb * CD * HW;
    const float* Bm = fs + (size_t)lb * CD * HW;
    int ij0 = blockIdx.y * 100, km0 = blockIdx.x * 200;

    __shared__ float As[16][100];
    __shared__ float Bs[16][200];
    int tid = threadIdx.x;
    int tx = tid % 20, ty = tid / 20;

    u64 acc[5][5];
    #pragma unroll
    for (int r = 0; r < 5; r++)
        #pragma unroll
        for (int s = 0; s < 5; s++) acc[r][s] = 0ull;

    int ka = tid / 25,  va = (tid % 25) * 4;
    int kb0 = tid / 50, vb0 = (tid % 50) * 4;
    int kb1 = (tid + 400) / 50, vb1 = ((tid + 400) % 50) * 4;
    const float* Ap  = A  + (size_t)ka  * HW + ij0 + va;
    const float* Bp0 = Bm + (size_t)kb0 * HW + km0 + vb0;
    const float* Bp1 = Bm + (size_t)kb1 * HW + km0 + vb1;

    float4 pa  = *(const float4*)Ap;
    float4 pb0 = *(const float4*)Bp0;
    float4 pb1 = *(const float4*)Bp1;

    for (int c0 = 0; c0 < CD; c0 += 16) {
        *(float4*)&As[ka][va]   = pa;
        *(float4*)&Bs[kb0][vb0] = pb0;
        *(float4*)&Bs[kb1][vb1] = pb1;
        __syncthreads();
        if (c0 + 16 < CD) {
            pa  = *(const float4*)(Ap  + (size_t)(c0 + 16) * HW);
            pb0 = *(const float4*)(Bp0 + (size_t)(c0 + 16) * HW);
            pb1 = *(const float4*)(Bp1 + (size_t)(c0 + 16) * HW);
        }
        #pragma unroll
        for (int kk = 0; kk < 16; kk++) {
            u64 a[5], b[5];
            #pragma unroll
            for (int r = 0; r < 5; r++) {
                float av = As[kk][r * 20 + ty];
                a[r] = pack2(av, av);
            }
            #pragma unroll
            for (int s = 0; s < 5; s++)
                b[s] = *(const u64*)&Bs[kk][tx * 10 + 2 * s];
            #pragma unroll
            for (int r = 0; r < 5; r++)
                #pragma unroll
                for (int s = 0; s < 5; s++) fma2(acc[r][s], a[r], b[s]);
        }
        __syncthreads();
    }

    int b = lb & 1, l = lb >> 1;
    const float* iq = invn + (size_t)lb * HW;
    const float* is = invn + NLB * HW + (size_t)lb * HW;
    float* cp = corr + (size_t)(b * LCH + l) * HW * HW;
    #pragma unroll
    for (int r = 0; r < 5; r++) {
        int ij = ij0 + r * 20 + ty;
        float sq = iq[ij];
        #pragma unroll
        for (int s = 0; s < 5; s++) {
            int col = km0 + tx * 10 + 2 * s;
            float2 isv = *(const float2*)&is[col];
            float lo, hi;
            unpack2(acc[r][s], lo, hi);
            float2 o;
            o.x = lo * sq * isv.x;
            o.y = hi * sq * isv.y;
            *(float2*)&cp[(size_t)ij * HW + col] = o;
        }
    }
}

// ---------------- interleave: out[ij][km] = (A[ij][km], A[km][ij]) ----------------
__global__ void transI_k(const float* __restrict__ in, float* __restrict__ out) {
    __shared__ float t1[32][33];
    __shared__ float t2[32][33];
    int mtx = blockIdx.z;
    const float* A = in + (size_t)mtx * HW * HW;
    float* O = out + (size_t)mtx * HW * HW * 2;
    int x0 = blockIdx.x * 32, y0 = blockIdx.y * 32;
    int tx = threadIdx.x, ty = threadIdx.y;
    #pragma unroll
    for (int r = 0; r < 32; r += 8) {
        int yy = y0 + ty + r, xx = x0 + tx;
        t1[ty + r][tx] = (yy < HW && xx < HW) ? A[(size_t)yy * HW + xx] : 0.f;
        int y2 = x0 + ty + r, x2 = y0 + tx;
        t2[ty + r][tx] = (y2 < HW && x2 < HW) ? A[(size_t)y2 * HW + x2] : 0.f;
    }
    __syncthreads();
    #pragma unroll
    for (int r = 0; r < 32; r += 8) {
        int ij = y0 + ty + r, km = x0 + tx;
        if (ij < HW && km < HW) {
            float2 o;
            o.x = t1[ty + r][tx];
            o.y = t2[tx][ty + r];
            *(float2*)&O[((size_t)ij * HW + km) * 2] = o;
        }
    }
}

// ---------------- pipelined 4D conv (NT=200 only): double-buffered 3-plane stages ----------
// Register-prefetch staging overlaps LDG latency with compute; one sync per stage.
template <int CIN, int COUT, int CO2, int PK, int PM, int MAXB>
__global__ void __launch_bounds__(200, MAXB) conv4d_pipe_k(
        const float* __restrict__ x, const u64* __restrict__ wd,
        float* __restrict__ y) {
    constexpr int NT = 200;
    constexpr int NPM = 20 / PM;
    constexpr int NPATCH = (20 / PK) * (20 / PM);
    constexpr int WTOT = 81 * COUT;

    __shared__ u64 sp2[2][3 * 484];     // double-buffered 3 padded planes
    __shared__ u64 wc2[2][WTOT];        // double-buffered dup weights

    int bij = blockIdx.x;
    int bb = bij / HW, ij = bij % HW;
    int i = ij / 20, j = ij % 20;
    int tid = threadIdx.x;
    int cobase = (tid / NPATCH) * CO2;
    int pid = tid % NPATCH;
    int k0 = (pid / NPM) * PK;
    int m0 = (pid % NPM) * PM;

    for (int t = tid; t < 2 * 3 * 484; t += NT)
        sp2[t / (3 * 484)][t % (3 * 484)] = 0ull;
    __syncthreads();   // pad-zero must complete before ANY staging writes (R12 bug fix)

    bool pok[9];
    int  po[9];
    #pragma unroll
    for (int p = 0; p < 9; p++) {
        int di = p / 3, dj = p % 3;
        int ii = i + di - 1, jj = j + dj - 1;
        pok[p] = ((unsigned)ii < 20u) && ((unsigned)jj < 20u);
        po[p]  = (ii * 20 + jj) * 800;
    }
    // NT=200: each thread owns quantum (r,c2) in each of 3 planes
    int rq = tid / 10, c2q = (tid % 10) * 2;
    int soff = (rq * 20 + c2q) * 2;
    int doff = (rq + 1) * 22 + (c2q + 1);

    u64 acc[CO2][PK][PM];
    #pragma unroll
    for (int c = 0; c < CO2; c++)
        #pragma unroll
        for (int pk = 0; pk < PK; pk++)
            #pragma unroll
            for (int pm = 0; pm < PM; pm++) acc[c][pk][pm] = 0ull;

    const float* xb = x + (size_t)bb * CIN * 320000;

    // prologue: weights ci0 + plane group (ci0, di0) into buffer 0
    for (int t = tid; t < WTOT; t += NT) wc2[0][t] = wd[t];
    #pragma unroll
    for (int p = 0; p < 3; p++) {
        ulonglong2 v = make_ulonglong2(0ull, 0ull);
        if (pok[p]) v = *(const ulonglong2*)(xb + po[p] + soff);
        u64* dst = &sp2[0][p * 484 + doff];
        dst[0] = v.x;
        dst[1] = v.y;
    }
    __syncthreads();

    for (int s = 0; s < 3 * CIN; s++) {
        int ci = s / 3, di = s % 3;
        int cur = s & 1;
        bool havenext = (s + 1 < 3 * CIN);

        // 1. prefetch next plane group into regs (LDG issues, latency covered by compute)
        ulonglong2 pf[3];
        if (havenext) {
            int nci = (di == 2) ? ci + 1 : ci;
            int ndi = (di == 2) ? 0 : di + 1;
            const float* xci = xb + (size_t)nci * 320000;
            #pragma unroll
            for (int p = 0; p < 3; p++) {
                int gp = ndi * 3 + p;
                pf[p] = make_ulonglong2(0ull, 0ull);
                if (pok[gp]) pf[p] = *(const ulonglong2*)(xci + po[gp] + soff);
            }
        }
        // weight prefetch for ci+1, split across di==0 (600) and di==1 (210) stages
        u64 wpf[3];
        int nwl = 0, wbase = 0;
        if (ci + 1 < CIN) {
            if (di == 0) { nwl = 3; wbase = 0; }
            else if (di == 1) { nwl = (WTOT > 600) ? 2 : 0; wbase = 600; }
        }
        for (int q2 = 0; q2 < nwl; q2++) {
            int t = wbase + tid + q2 * NT;
            wpf[q2] = (t < WTOT) ? wd[(size_t)(ci + 1) * WTOT + t] : 0ull;
        }

        // 2. compute 3 dij from current buffer
        const u64* wb = wc2[ci & 1];
        #pragma unroll
        for (int dj = 0; dj < 3; dj++) {
            int dij = di * 3 + dj;
            const u64* P = &sp2[cur][dj * 484 + k0 * 22 + m0];
            u64 w2[CO2][9];
            #pragma unroll
            for (int t = 0; t < 9; t++) {
                if (CO2 == 2) {
                    ulonglong2 wv = *(const ulonglong2*)&wb[(dij * 9 + t) * COUT + cobase];
                    w2[0][t] = wv.x;
                    w2[CO2 - 1][t] = wv.y;
                } else {
                    w2[0][t] = wb[(dij * 9 + t) * COUT + cobase];
                }
            }
            #pragma unroll
            for (int r = 0; r < PK + 2; r++) {
                u64 xr[PM + 2];
                #pragma unroll
                for (int h = 0; h < (PM + 2) / 2; h++) {
                    ulonglong2 v = *(const ulonglong2*)&P[r * 22 + 2 * h];
                    xr[2 * h] = v.x;
                    xr[2 * h + 1] = v.y;
                }
                #pragma unroll
                for (int dk = 0; dk < 3; dk++) {
                    int pk = r - dk;
                    if (pk < 0 || pk >= PK) continue;
                    #pragma unroll
                    for (int dm = 0; dm < 3; dm++)
                        #pragma unroll
                        for (int c = 0; c < CO2; c++)
                            #pragma unroll
                            for (int pm = 0; pm < PM; pm++)
                                fma2(acc[c][pk][pm], xr[pm + dm], w2[c][dk * 3 + dm]);
                }
            }
        }

        // 3. store prefetched data to alternate buffers
        if (havenext) {
            #pragma unroll
            for (int p = 0; p < 3; p++) {
                u64* dst = &sp2[1 - cur][p * 484 + doff];
                dst[0] = pf[p].x;
                dst[1] = pf[p].y;
            }
        }
        for (int q2 = 0; q2 < nwl; q2++) {
            int t = wbase + tid + q2 * NT;
            if (t < WTOT) wc2[(ci + 1) & 1][t] = wpf[q2];
        }
        __syncthreads();
    }

    #pragma unroll
    for (int c = 0; c < CO2; c++) {
        float* yp = y + (((size_t)(bb * COUT + cobase + c) * 400 + ij) * 400) * 2;
        #pragma unroll
        for (int pk = 0; pk < PK; pk++)
            #pragma unroll
            for (int pm = 0; pm < PM; pm++) {
                float lo, hi;
                unpack2(acc[c][pk][pm], lo, hi);
                float2 o;
                o.x = fmaxf(lo, 0.f);
                o.y = fmaxf(hi, 0.f);
                *(float2*)&yp[((k0 + pk) * 20 + m0 + pm) * 2] = o;
            }
    }
}

// ---------------- unpipelined 4D conv (for small layer 3) ----------------
template <int CIN, int COUT, int CO2, int PK, int PM, int NT, int MAXB>
__global__ void __launch_bounds__(NT, MAXB) conv4d_k(
        const float* __restrict__ x, const u64* __restrict__ wd,
        float* __restrict__ y) {
    constexpr int NPK = 20 / PK, NPM = 20 / PM;
    constexpr int NPATCH = NPK * NPM;
    constexpr int NSTG = 200 / NT;

    __shared__ u64 sp2[9 * 484];
    __shared__ u64 wc2[81 * COUT];

    int bij = blockIdx.x;
    int bb = bij / HW, ij = bij % HW;
    int i = ij / 20, j = ij % 20;
    int tid = threadIdx.x;
    int cobase = (tid / NPATCH) * CO2;
    int pid = tid % NPATCH;
    int k0 = (pid / NPM) * PK;
    int m0 = (pid % NPM) * PM;

    for (int t = tid; t < 9 * 484; t += NT) sp2[t] = 0ull;

    bool pok[9];
    int  po[9];
    #pragma unroll
    for (int p = 0; p < 9; p++) {
        int di = p / 3, dj = p % 3;
        int ii = i + di - 1, jj = j + dj - 1;
        pok[p] = ((unsigned)ii < 20u) && ((unsigned)jj < 20u);
        po[p]  = (ii * 20 + jj) * 800;
    }
    int  soff[NSTG];
    int  doff[NSTG];
    #pragma unroll
    for (int q = 0; q < NSTG; q++) {
        int rem2 = tid + q * NT;
        int r = rem2 / 10, c2 = (rem2 % 10) * 2;
        soff[q] = (r * 20 + c2) * 2;
        doff[q] = (r + 1) * 22 + (c2 + 1);
    }

    u64 acc[CO2][PK][PM];
    #pragma unroll
    for (int c = 0; c < CO2; c++)
        #pragma unroll
        for (int pk = 0; pk < PK; pk++)
            #pragma unroll
            for (int pm = 0; pm < PM; pm++) acc[c][pk][pm] = 0ull;

    const float* xb = x + (size_t)bb * CIN * 320000;

    for (int ci = 0; ci < CIN; ci++) {
        __syncthreads();
        for (int t = tid; t < 81 * COUT; t += NT)
            wc2[t] = wd[(size_t)ci * 81 * COUT + t];
        const float* xci = xb + (size_t)ci * 320000;
        #pragma unroll
        for (int p = 0; p < 9; p++) {
            #pragma unroll
            for (int q = 0; q < NSTG; q++) {
                ulonglong2 v = make_ulonglong2(0ull, 0ull);
                if (pok[p]) v = *(const ulonglong2*)(xci + po[p] + soff[q]);
                u64* dst = &sp2[p * 484 + doff[q]];
                dst[0] = v.x;
                dst[1] = v.y;
            }
        }
        __syncthreads();

        #pragma unroll
        for (int dij = 0; dij < 9; dij++) {
            const u64* P = sp2 + dij * 484 + k0 * 22 + m0;
            u64 w2[CO2][9];
            #pragma unroll
            for (int t = 0; t < 9; t++) {
                if (CO2 == 2) {
                    ulonglong2 wv = *(const ulonglong2*)&wc2[(dij * 9 + t) * COUT + cobase];
                    w2[0][t] = wv.x;
                    w2[CO2 - 1][t] = wv.y;
                } else {
                    w2[0][t] = wc2[(dij * 9 + t) * COUT + cobase];
                }
            }
            #pragma unroll
            for (int r = 0; r < PK + 2; r++) {
                u64 xr[PM + 2];
                #pragma unroll
                for (int h = 0; h < (PM + 2) / 2; h++) {
                    ulonglong2 v = *(const ulonglong2*)&P[r * 22 + 2 * h];
                    xr[2 * h] = v.x;
                    xr[2 * h + 1] = v.y;
                }
                #pragma unroll
                for (int dk = 0; dk < 3; dk++) {
                    int pk = r - dk;
                    if (pk < 0 || pk >= PK) continue;
                    #pragma unroll
                    for (int dm = 0; dm < 3; dm++)
                        #pragma unroll
                        for (int c = 0; c < CO2; c++)
                            #pragma unroll
                            for (int pm = 0; pm < PM; pm++)
                                fma2(acc[c][pk][pm], xr[pm + dm], w2[c][dk * 3 + dm]);
                }
            }
        }
    }

    #pragma unroll
    for (int c = 0; c < CO2; c++) {
        float* yp = y + (((size_t)(bb * COUT + cobase + c) * 400 + ij) * 400) * 2;
        #pragma unroll
        for (int pk = 0; pk < PK; pk++)
            #pragma unroll
            for (int pm = 0; pm < PM; pm++) {
                float lo, hi;
                unpack2(acc[c][pk][pm], lo, hi);
                float2 o;
                o.x = fmaxf(lo, 0.f);
                o.y = fmaxf(hi, 0.f);
                *(float2*)&yp[((k0 + pk) * 20 + m0 + pm) * 2] = o;
            }
    }
}

// ---------------- combine branches: c4[q][s] = I[q][s].x + I[s][q].y ----------------
__global__ void addt2_k(const float* __restrict__ I, float* __restrict__ o) {
    __shared__ float t1[32][33];
    __shared__ float t2[32][33];
    int b = blockIdx.z;
    const float* Ib = I + (size_t)b * HW * HW * 2;
    float* O = o + (size_t)b * HW * HW;
    int q0 = blockIdx.y * 32, s0 = blockIdx.x * 32;
    int tx = threadIdx.x, ty = threadIdx.y;
    #pragma unroll
    for (int r = 0; r < 32; r += 8) {
        int q = q0 + ty + r, s = s0 + tx;
        t1[ty + r][tx] = (q < HW && s < HW) ? Ib[((size_t)q * HW + s) * 2] : 0.f;
        int s2 = s0 + ty + r, q2 = q0 + tx;
        t2[ty + r][tx] = (s2 < HW && q2 < HW) ? Ib[((size_t)s2 * HW + q2) * 2 + 1] : 0.f;
    }
    __syncthreads();
    #pragma unroll
    for (int r = 0; r < 32; r += 8) {
        int q = q0 + ty + r, s = s0 + tx;
        if (q < HW && s < HW) O[(size_t)q * HW + s] = t1[ty + r][tx] + t2[tx][ty + r];
    }
}

// ---------------- softmax ----------------
__global__ void softmax_k(const float* __restrict__ x, float* __restrict__ y) {
    int row = blockIdx.x;
    const float* xr = x + (size_t)row * HW;
    float*       yr = y + (size_t)row * HW;
    __shared__ float sh[HW];
    __shared__ float red[4];
    int tid = threadIdx.x;
    float mx = -3.4e38f;
    for (int i = tid; i < HW; i += 128) {
        float v = xr[i] * TEMP;
        sh[i] = v;
        mx = fmaxf(mx, v);
    }
    #pragma unroll
    for (int o = 16; o; o >>= 1) mx = fmaxf(mx, __shfl_xor_sync(0xffffffffu, mx, o));
    if ((tid & 31) == 0) red[tid >> 5] = mx;
    __syncthreads();
    mx = fmaxf(fmaxf(red[0], red[1]), fmaxf(red[2], red[3]));
    float sum = 0.f;
    for (int i = tid; i < HW; i += 128) {
        float e = expf(sh[i] - mx);
        sh[i] = e;
        sum += e;
    }
    #pragma unroll
    for (int o = 16; o; o >>= 1) sum += __shfl_xor_sync(0xffffffffu, sum, o);
    __syncthreads();
    if ((tid & 31) == 0) red[tid >> 5] = sum;
    __syncthreads();
    float inv = 1.f / (red[0] + red[1] + red[2] + red[3]);
    for (int i = tid; i < HW; i += 128) yr[i] = sh[i] * inv;
}

// ---------------- attention GEMM (NT) ----------------
__global__ void attn_gemm_k(const float* __restrict__ attn, const float* __restrict__ v,
                            float* __restrict__ out) {
    int b = blockIdx.z;
    const float* A = v    + (size_t)b * CH * HW;
    const float* P = attn + (size_t)b * HW * HW;
    int c0 = blockIdx.y * 64, q0 = blockIdx.x * 64;

    __shared__ float As[16][65];
    __shared__ float Ps[16][65];
    int tid = threadIdx.x;
    int tx = tid & 15, ty = tid >> 4;
    float acc[4][4] = {};

    for (int s0 = 0; s0 < HW; s0 += 16) {
        #pragma unroll
        for (int t = tid; t < 1024; t += 256) {
            int row = t >> 4, kk = t & 15;
            int c = c0 + row, q = q0 + row;
            As[kk][row] = (c < CH) ? A[(size_t)c * HW + s0 + kk] : 0.f;
            Ps[kk][row] = (q < HW) ? P[(size_t)q * HW + s0 + kk] : 0.f;
        }
        __syncthreads();
        #pragma unroll
        for (int kk = 0; kk < 16; kk++) {
            float a[4], p[4];
            #pragma unroll
            for (int r = 0; r < 4; r++) { a[r] = As[kk][ty * 4 + r]; p[r] = Ps[kk][tx * 4 + r]; }
            #pragma unroll
            for (int r = 0; r < 4; r++)
                #pragma unroll
                for (int s = 0; s < 4; s++) acc[r][s] += a[r] * p[s];
        }
        __syncthreads();
    }
    #pragma unroll
    for (int r = 0; r < 4; r++) {
        int c = c0 + ty * 4 + r;
        if (c >= CH) continue;
        #pragma unroll
        for (int s = 0; s < 4; s++) {
            int q = q0 + tx * 4 + s;
            if (q < HW) out[((size_t)b * CH + c) * HW + q] = acc[r][s];
        }
    }
}

// ---------------- final norms + combine ----------------
__global__ void norm2_k(const float* __restrict__ fqin, const float* __restrict__ att,
                        float* __restrict__ nrm) {
    int b = blockIdx.x, z = blockIdx.y;
    const float* x = (z ? att : fqin) + (size_t)b * CH * HW + threadIdx.x;
    float s = 0.f;
    #pragma unroll 8
    for (int c = 0; c < CH; c++) {
        float v = x[(size_t)c * HW];
        s += v * v;
    }
    nrm[(z * BS + b) * HW + threadIdx.x] = 1.f / fmaxf(sqrtf(s), 1e-12f);
}

__global__ void combine_k(const float* __restrict__ fqin, const float* __restrict__ att,
                          const float* __restrict__ nrm, float* __restrict__ out) {
    int idx = blockIdx.x * blockDim.x + threadIdx.x;
    if (idx >= BS * CH * HW) return;
    int b = idx / (CH * HW);
    int pos = idx % HW;
    out[idx] = fqin[idx] * nrm[b * HW + pos] + att[idx] * nrm[(BS + b) * HW + pos] * 0.5f;
}

// ---------------- launch ----------------
extern "C" void kernel_launch(void* const* d_in, const int* in_sizes, int n_in,
                              void* d_out, int out_size) {
    const float* fqf = (const float*)d_in[0];
    const float* fsf = (const float*)d_in[1];
    const float* f_q = (const float*)d_in[2];
    const float* f_s = (const float*)d_in[3];
    const float* w1  = (const float*)d_in[4];
    const float* w2  = (const float*)d_in[5];
    const float* w3  = (const float*)d_in[6];
    float* out = (float*)d_out;

    float *part, *invn, *corr, *corrI, *buf1, *buf2, *c4ab, *c4, *attn, *nrm;
    int* cnt;
    u64 *wd1, *wd2, *wd3;
    cudaGetSymbolAddress((void**)&part,  g_part);
    cudaGetSymbolAddress((void**)&cnt,   g_cnt);
    cudaGetSymbolAddress((void**)&invn,  g_invn);
    cudaGetSymbolAddress((void**)&corr,  g_corr);
    cudaGetSymbolAddress((void**)&corrI, g_corrI);
    cudaGetSymbolAddress((void**)&buf1,  g_buf1I);
    cudaGetSymbolAddress((void**)&buf2,  g_buf2I);
    cudaGetSymbolAddress((void**)&c4ab,  g_c4abI);
    cudaGetSymbolAddress((void**)&c4,    g_c4);
    cudaGetSymbolAddress((void**)&attn,  g_attn);
    cudaGetSymbolAddress((void**)&nrm,   g_nrm);
    cudaGetSymbolAddress((void**)&wd1,   g_wd1);
    cudaGetSymbolAddress((void**)&wd2,   g_wd2);
    cudaGetSymbolAddress((void**)&wd3,   g_wd3);

    // 1. prep: full-chip sumsq + last-block reduce + weight dup
    prep_k<<<dim3(NLB, 2, 8), 400>>>(fqf, fsf, part, cnt, invn, w1, w2, w3, wd1, wd2, wd3);

    // 2. correlation tensor
    corr_gemm_k<<<dim3(2, 4, NLB), 400>>>(fqf, fsf, invn, corr);

    // 3. branch-interleave
    transI_k<<<dim3(13, 13, NLB), dim3(32, 8)>>>(corr, corrI);

    // 4. neighborhood consensus (launch #4 = conv1 pipe -> ncu capture)
    conv4d_pipe_k<9, 10, 2, 5, 2, 3><<<BS * HW, 200>>>(corrI, wd1, buf1);
    conv4d_pipe_k<10, 10, 2, 5, 2, 3><<<BS * HW, 200>>>(buf1, wd2, buf2);
    conv4d_k<10, 1, 1, 2, 2, 100, 4><<<BS * HW, 100>>>(buf2, wd3, c4ab);

    // 5. combine branches
    addt2_k<<<dim3(13, 13, BS), dim3(32, 8)>>>(c4ab, c4);

    // 6. softmax + attention
    softmax_k<<<BS * HW, 128>>>(c4, attn);
    attn_gemm_k<<<dim3(7, 4, BS), 256>>>(attn, f_s, out + BS * CH * HW);

    // 7. final L2-norm combine
    norm2_k<<<dim3(BS, 2), 400>>>(f_q, out + BS * CH * HW, nrm);
    combine_k<<<(BS * CH * HW + 255) / 256, 256>>>(f_q, out + BS * CH * HW, nrm, out);
}

// round 14
// speedup vs baseline: 1.0342x; 1.0342x over previous
#include <cuda_runtime.h>
#include <math.h>
#include <stdint.h>

#define HW   400
#define LCH  9
#define BS   2
#define CD   1024
#define CH   256
#define NLB  18
#define TEMP 20.0f

typedef unsigned long long u64;

// ---------------- scratch ----------------
__device__ float g_part [2 * NLB * 8 * HW];
__device__ int   g_cnt  [2 * NLB];
__device__ float g_invn [2 * NLB * HW];
__device__ float g_corrP[(size_t)2 * NLB * HW * HW];        // two K-split partials (raw dots)
__device__ float g_corrI[(size_t)NLB * HW * HW * 2];        // (corr, corrT) interleaved, scaled
__device__ float g_buf1I[(size_t)BS * 10 * HW * HW * 2];
__device__ float g_buf2I[(size_t)BS * 10 * HW * HW * 2];
__device__ float g_c4abI[(size_t)BS * HW * HW * 2];
__device__ float g_c4   [BS * HW * HW];
__device__ float g_attn [BS * HW * HW];
__device__ float g_nrm  [2 * BS * HW];
__device__ u64   g_wd1  [9 * 81 * 10];
__device__ u64   g_wd2  [10 * 81 * 10];
__device__ u64   g_wd3  [10 * 81 * 1];

// ---------------- f32x2 helpers ----------------
__device__ __forceinline__ u64 pack2(float x, float y) {
    u64 r;
    asm("mov.b64 %0, {%1, %2};" : "=l"(r) : "f"(x), "f"(y));
    return r;
}
__device__ __forceinline__ void unpack2(u64 v, float& x, float& y) {
    asm("mov.b64 {%0, %1}, %2;" : "=f"(x), "=f"(y) : "l"(v));
}
__device__ __forceinline__ void fma2(u64& d, u64 a, u64 b) {
    asm("fma.rn.f32x2 %0, %1, %2, %0;" : "+l"(d) : "l"(a), "l"(b));
}

// ---------------- prep: full-chip partial sumsq + last-block reduce + weight dup ----------------
__global__ void prep_k(const float* __restrict__ fq, const float* __restrict__ fs,
                       float* __restrict__ part, int* __restrict__ cnt,
                       float* __restrict__ inv,
                       const float* __restrict__ w1, const float* __restrict__ w2,
                       const float* __restrict__ w3,
                       u64* __restrict__ o1, u64* __restrict__ o2, u64* __restrict__ o3) {
    int z = blockIdx.y, lb = blockIdx.x, ch = blockIdx.z;
    int pos = threadIdx.x;
    const float* x = (z ? fs : fq) + ((size_t)lb * CD + ch * 128) * HW + pos;
    float s0 = 0.f, s1 = 0.f, s2 = 0.f, s3 = 0.f;
    #pragma unroll 4
    for (int c = 0; c < 128; c += 4) {
        float v0 = x[(size_t)(c + 0) * HW];
        float v1 = x[(size_t)(c + 1) * HW];
        float v2 = x[(size_t)(c + 2) * HW];
        float v3 = x[(size_t)(c + 3) * HW];
        s0 += v0 * v0; s1 += v1 * v1; s2 += v2 * v2; s3 += v3 * v3;
    }
    part[(((size_t)z * NLB + lb) * 8 + ch) * HW + pos] = (s0 + s1) + (s2 + s3);

    if (z == 0 && lb == 0 && ch == 0) {
        for (int idx = pos; idx < 10 * 81 * 10; idx += 400) {
            if (idx < 9 * 81 * 10) {
                int co = idx % 10, rem = idx / 10;
                int ci = rem / 81, tap = rem % 81;
                float w = w1[((size_t)co * 9 + ci) * 81 + tap];
                o1[idx] = pack2(w, w);
            }
            {
                int co = idx % 10, rem = idx / 10;
                int ci = rem / 81, tap = rem % 81;
                float w = w2[((size_t)co * 10 + ci) * 81 + tap];
                o2[idx] = pack2(w, w);
            }
            if (idx < 10 * 81) {
                float w = w3[idx];
                o3[idx] = pack2(w, w);
            }
        }
    }

    __threadfence();
    __syncthreads();
    __shared__ int lastflag;
    if (pos == 0) lastflag = (atomicAdd(&cnt[z * NLB + lb], 1) == 7) ? 1 : 0;
    __syncthreads();
    if (lastflag) {
        const float* p = part + ((size_t)z * NLB + lb) * 8 * HW + pos;
        float s = 0.f;
        #pragma unroll
        for (int c = 0; c < 8; c++) s += p[c * HW];
        inv[z * NLB * HW + lb * HW + pos] = 1.f / fmaxf(sqrtf(s), 1e-12f);
        if (pos == 0) cnt[z * NLB + lb] = 0;
    }
}

// ---------------- correlation GEMM (TN), FFMA2, K-split 2, raw partial outputs ----------------
// grid (2, 4, 36), block 400: tile 100 x 200, K-tile 16, K range 512/block.
// launch_bounds(400,2): 2 blocks/SM (25 warps) hides slab-sync latency.
__global__ void __launch_bounds__(400, 2) corr_gemm_k(
        const float* __restrict__ fq, const float* __restrict__ fs,
        float* __restrict__ corrP) {
    int zz = blockIdx.z;
    int lb = zz >> 1, ks = zz & 1;
    const float* A  = fq + (size_t)lb * CD * HW;
    const float* Bm = fs + (size_t)lb * CD * HW;
    int ij0 = blockIdx.y * 100, km0 = blockIdx.x * 200;

    __shared__ float As[16][100];
    __shared__ float Bs[16][200];
    int tid = threadIdx.x;
    int tx = tid % 20, ty = tid / 20;

    u64 acc[5][5];
    #pragma unroll
    for (int r = 0; r < 5; r++)
        #pragma unroll
        for (int s = 0; s < 5; s++) acc[r][s] = 0ull;

    int ka = tid / 25,  va = (tid % 25) * 4;
    int kb0 = tid / 50, vb0 = (tid % 50) * 4;
    int kb1 = (tid + 400) / 50, vb1 = ((tid + 400) % 50) * 4;
    const float* Ap  = A  + (size_t)ka  * HW + ij0 + va;
    const float* Bp0 = Bm + (size_t)kb0 * HW + km0 + vb0;
    const float* Bp1 = Bm + (size_t)kb1 * HW + km0 + vb1;

    int c0base = ks * (CD / 2);
    for (int c0 = c0base; c0 < c0base + CD / 2; c0 += 16) {
        *(float4*)&As[ka][va]   = *(const float4*)(Ap  + (size_t)c0 * HW);
        *(float4*)&Bs[kb0][vb0] = *(const float4*)(Bp0 + (size_t)c0 * HW);
        *(float4*)&Bs[kb1][vb1] = *(const float4*)(Bp1 + (size_t)c0 * HW);
        __syncthreads();
        #pragma unroll
        for (int kk = 0; kk < 16; kk++) {
            u64 a[5], b[5];
            #pragma unroll
            for (int r = 0; r < 5; r++) {
                float av = As[kk][r * 20 + ty];
                a[r] = pack2(av, av);
            }
            #pragma unroll
            for (int s = 0; s < 5; s++)
                b[s] = *(const u64*)&Bs[kk][tx * 10 + 2 * s];
            #pragma unroll
            for (int r = 0; r < 5; r++)
                #pragma unroll
                for (int s = 0; s < 5; s++) fma2(acc[r][s], a[r], b[s]);
        }
        __syncthreads();
    }

    int b = lb & 1, l = lb >> 1;
    float* cp = corrP + (size_t)ks * NLB * HW * HW + (size_t)(b * LCH + l) * HW * HW;
    #pragma unroll
    for (int r = 0; r < 5; r++) {
        int ij = ij0 + r * 20 + ty;
        #pragma unroll
        for (int s = 0; s < 5; s++) {
            int col = km0 + tx * 10 + 2 * s;
            float lo, hi;
            unpack2(acc[r][s], lo, hi);
            float2 o;
            o.x = lo;
            o.y = hi;
            *(float2*)&cp[(size_t)ij * HW + col] = o;
        }
    }
}

// ---------------- interleave + partial-sum + norm-scale ----------------
// out[ij][km] = ((P0+P1)[ij][km]*iq[ij]*is[km], (P0+P1)[km][ij]*iq[km]*is[ij])
__global__ void transI_k(const float* __restrict__ P0, const float* __restrict__ invn,
                         float* __restrict__ out) {
    __shared__ float t1[32][33];
    __shared__ float t2[32][33];
    int mtx = blockIdx.z;                         // plane m = b*LCH + l
    int b = mtx / LCH, l = mtx % LCH;
    int lb = l * BS + b;
    const float* iq = invn + (size_t)lb * HW;
    const float* is = invn + NLB * HW + (size_t)lb * HW;
    const float* A0 = P0 + (size_t)mtx * HW * HW;
    const float* A1 = A0 + (size_t)NLB * HW * HW;
    float* O = out + (size_t)mtx * HW * HW * 2;
    int x0 = blockIdx.x * 32, y0 = blockIdx.y * 32;
    int tx = threadIdx.x, ty = threadIdx.y;
    #pragma unroll
    for (int r = 0; r < 32; r += 8) {
        int yy = y0 + ty + r, xx = x0 + tx;
        t1[ty + r][tx] = (yy < HW && xx < HW)
            ? (A0[(size_t)yy * HW + xx] + A1[(size_t)yy * HW + xx]) * iq[yy] * is[xx] : 0.f;
        int y2 = x0 + ty + r, x2 = y0 + tx;
        t2[ty + r][tx] = (y2 < HW && x2 < HW)
            ? (A0[(size_t)y2 * HW + x2] + A1[(size_t)y2 * HW + x2]) * iq[y2] * is[x2] : 0.f;
    }
    __syncthreads();
    #pragma unroll
    for (int r = 0; r < 32; r += 8) {
        int ij = y0 + ty + r, km = x0 + tx;
        if (ij < HW && km < HW) {
            float2 o;
            o.x = t1[ty + r][tx];
            o.y = t2[tx][ty + r];
            *(float2*)&O[((size_t)ij * HW + km) * 2] = o;
        }
    }
}

// ---------------- 4D conv (3x3x3x3, pad 1, relu), branch-pair FFMA2 (R11 config) ----------
template <int CIN, int COUT, int CO2, int PK, int PM, int NT, int MAXB>
__global__ void __launch_bounds__(NT, MAXB) conv4d_k(
        const float* __restrict__ x, const u64* __restrict__ wd,
        float* __restrict__ y) {
    constexpr int NPK = 20 / PK, NPM = 20 / PM;
    constexpr int NPATCH = NPK * NPM;
    constexpr int NSTG = 200 / NT;

    __shared__ u64 sp2[9 * 484];
    __shared__ u64 wc2[81 * COUT];

    int bij = blockIdx.x;
    int bb = bij / HW, ij = bij % HW;
    int i = ij / 20, j = ij % 20;
    int tid = threadIdx.x;
    int cobase = (tid / NPATCH) * CO2;
    int pid = tid % NPATCH;
    int k0 = (pid / NPM) * PK;
    int m0 = (pid % NPM) * PM;

    for (int t = tid; t < 9 * 484; t += NT) sp2[t] = 0ull;

    bool pok[9];
    int  po[9];
    #pragma unroll
    for (int p = 0; p < 9; p++) {
        int di = p / 3, dj = p % 3;
        int ii = i + di - 1, jj = j + dj - 1;
        pok[p] = ((unsigned)ii < 20u) && ((unsigned)jj < 20u);
        po[p]  = (ii * 20 + jj) * 800;
    }
    int  soff[NSTG];
    int  doff[NSTG];
    #pragma unroll
    for (int q = 0; q < NSTG; q++) {
        int rem2 = tid + q * NT;
        int r = rem2 / 10, c2 = (rem2 % 10) * 2;
        soff[q] = (r * 20 + c2) * 2;
        doff[q] = (r + 1) * 22 + (c2 + 1);
    }

    u64 acc[CO2][PK][PM];
    #pragma unroll
    for (int c = 0; c < CO2; c++)
        #pragma unroll
        for (int pk = 0; pk < PK; pk++)
            #pragma unroll
            for (int pm = 0; pm < PM; pm++) acc[c][pk][pm] = 0ull;

    const float* xb = x + (size_t)bb * CIN * 320000;

    for (int ci = 0; ci < CIN; ci++) {
        __syncthreads();
        for (int t = tid; t < 81 * COUT; t += NT)
            wc2[t] = wd[(size_t)ci * 81 * COUT + t];
        const float* xci = xb + (size_t)ci * 320000;
        #pragma unroll
        for (int p = 0; p < 9; p++) {
            #pragma unroll
            for (int q = 0; q < NSTG; q++) {
                ulonglong2 v = make_ulonglong2(0ull, 0ull);
                if (pok[p]) v = *(const ulonglong2*)(xci + po[p] + soff[q]);
                u64* dst = &sp2[p * 484 + doff[q]];
                dst[0] = v.x;
                dst[1] = v.y;
            }
        }
        __syncthreads();

        #pragma unroll
        for (int dij = 0; dij < 9; dij++) {
            const u64* P = sp2 + dij * 484 + k0 * 22 + m0;
            u64 w2[CO2][9];
            #pragma unroll
            for (int t = 0; t < 9; t++) {
                if (CO2 == 2) {
                    ulonglong2 wv = *(const ulonglong2*)&wc2[(dij * 9 + t) * COUT + cobase];
                    w2[0][t] = wv.x;
                    w2[CO2 - 1][t] = wv.y;
                } else {
                    w2[0][t] = wc2[(dij * 9 + t) * COUT + cobase];
                }
            }
            #pragma unroll
            for (int r = 0; r < PK + 2; r++) {
                u64 xr[PM + 2];
                #pragma unroll
                for (int h = 0; h < (PM + 2) / 2; h++) {
                    ulonglong2 v = *(const ulonglong2*)&P[r * 22 + 2 * h];
                    xr[2 * h] = v.x;
                    xr[2 * h + 1] = v.y;
                }
                #pragma unroll
                for (int dk = 0; dk < 3; dk++) {
                    int pk = r - dk;
                    if (pk < 0 || pk >= PK) continue;
                    #pragma unroll
                    for (int dm = 0; dm < 3; dm++)
                        #pragma unroll
                        for (int c = 0; c < CO2; c++)
                            #pragma unroll
                            for (int pm = 0; pm < PM; pm++)
                                fma2(acc[c][pk][pm], xr[pm + dm], w2[c][dk * 3 + dm]);
                }
            }
        }
    }

    #pragma unroll
    for (int c = 0; c < CO2; c++) {
        float* yp = y + (((size_t)(bb * COUT + cobase + c) * 400 + ij) * 400) * 2;
        #pragma unroll
        for (int pk = 0; pk < PK; pk++)
            #pragma unroll
            for (int pm = 0; pm < PM; pm++) {
                float lo, hi;
                unpack2(acc[c][pk][pm], lo, hi);
                float2 o;
                o.x = fmaxf(lo, 0.f);
                o.y = fmaxf(hi, 0.f);
                *(float2*)&yp[((k0 + pk) * 20 + m0 + pm) * 2] = o;
            }
    }
}

// ---------------- combine branches: c4[q][s] = I[q][s].x + I[s][q].y ----------------
__global__ void addt2_k(const float* __restrict__ I, float* __restrict__ o) {
    __shared__ float t1[32][33];
    __shared__ float t2[32][33];
    int b = blockIdx.z;
    const float* Ib = I + (size_t)b * HW * HW * 2;
    float* O = o + (size_t)b * HW * HW;
    int q0 = blockIdx.y * 32, s0 = blockIdx.x * 32;
    int tx = threadIdx.x, ty = threadIdx.y;
    #pragma unroll
    for (int r = 0; r < 32; r += 8) {
        int q = q0 + ty + r, s = s0 + tx;
        t1[ty + r][tx] = (q < HW && s < HW) ? Ib[((size_t)q * HW + s) * 2] : 0.f;
        int s2 = s0 + ty + r, q2 = q0 + tx;
        t2[ty + r][tx] = (s2 < HW && q2 < HW) ? Ib[((size_t)s2 * HW + q2) * 2 + 1] : 0.f;
    }
    __syncthreads();
    #pragma unroll
    for (int r = 0; r < 32; r += 8) {
        int q = q0 + ty + r, s = s0 + tx;
        if (q < HW && s < HW) O[(size_t)q * HW + s] = t1[ty + r][tx] + t2[tx][ty + r];
    }
}

// ---------------- softmax ----------------
__global__ void softmax_k(const float* __restrict__ x, float* __restrict__ y) {
    int row = blockIdx.x;
    const float* xr = x + (size_t)row * HW;
    float*       yr = y + (size_t)row * HW;
    __shared__ float sh[HW];
    __shared__ float red[4];
    int tid = threadIdx.x;
    float mx = -3.4e38f;
    for (int i = tid; i < HW; i += 128) {
        float v = xr[i] * TEMP;
        sh[i] = v;
        mx = fmaxf(mx, v);
    }
    #pragma unroll
    for (int o = 16; o; o >>= 1) mx = fmaxf(mx, __shfl_xor_sync(0xffffffffu, mx, o));
    if ((tid & 31) == 0) red[tid >> 5] = mx;
    __syncthreads();
    mx = fmaxf(fmaxf(red[0], red[1]), fmaxf(red[2], red[3]));
    float sum = 0.f;
    for (int i = tid; i < HW; i += 128) {
        float e = expf(sh[i] - mx);
        sh[i] = e;
        sum += e;
    }
    #pragma unroll
    for (int o = 16; o; o >>= 1) sum += __shfl_xor_sync(0xffffffffu, sum, o);
    __syncthreads();
    if ((tid & 31) == 0) red[tid >> 5] = sum;
    __syncthreads();
    float inv = 1.f / (red[0] + red[1] + red[2] + red[3]);
    for (int i = tid; i < HW; i += 128) yr[i] = sh[i] * inv;
}

// ---------------- attention GEMM (NT) ----------------
__global__ void attn_gemm_k(const float* __restrict__ attn, const float* __restrict__ v,
                            float* __restrict__ out) {
    int b = blockIdx.z;
    const float* A = v    + (size_t)b * CH * HW;
    const float* P = attn + (size_t)b * HW * HW;
    int c0 = blockIdx.y * 64, q0 = blockIdx.x * 64;

    __shared__ float As[16][65];
    __shared__ float Ps[16][65];
    int tid = threadIdx.x;
    int tx = tid & 15, ty = tid >> 4;
    float acc[4][4] = {};

    for (int s0 = 0; s0 < HW; s0 += 16) {
        #pragma unroll
        for (int t = tid; t < 1024; t += 256) {
            int row = t >> 4, kk = t & 15;
            int c = c0 + row, q = q0 + row;
            As[kk][row] = (c < CH) ? A[(size_t)c * HW + s0 + kk] : 0.f;
            Ps[kk][row] = (q < HW) ? P[(size_t)q * HW + s0 + kk] : 0.f;
        }
        __syncthreads();
        #pragma unroll
        for (int kk = 0; kk < 16; kk++) {
            float a[4], p[4];
            #pragma unroll
            for (int r = 0; r < 4; r++) { a[r] = As[kk][ty * 4 + r]; p[r] = Ps[kk][tx * 4 + r]; }
            #pragma unroll
            for (int r = 0; r < 4; r++)
                #pragma unroll
                for (int s = 0; s < 4; s++) acc[r][s] += a[r] * p[s];
        }
        __syncthreads();
    }
    #pragma unroll
    for (int r = 0; r < 4; r++) {
        int c = c0 + ty * 4 + r;
        if (c >= CH) continue;
        #pragma unroll
        for (int s = 0; s < 4; s++) {
            int q = q0 + tx * 4 + s;
            if (q < HW) out[((size_t)b * CH + c) * HW + q] = acc[r][s];
        }
    }
}

// ---------------- final norms + combine ----------------
__global__ void norm2_k(const float* __restrict__ fqin, const float* __restrict__ att,
                        float* __restrict__ nrm) {
    int b = blockIdx.x, z = blockIdx.y;
    const float* x = (z ? att : fqin) + (size_t)b * CH * HW + threadIdx.x;
    float s = 0.f;
    #pragma unroll 8
    for (int c = 0; c < CH; c++) {
        float v = x[(size_t)c * HW];
        s += v * v;
    }
    nrm[(z * BS + b) * HW + threadIdx.x] = 1.f / fmaxf(sqrtf(s), 1e-12f);
}

__global__ void combine_k(const float* __restrict__ fqin, const float* __restrict__ att,
                          const float* __restrict__ nrm, float* __restrict__ out) {
    int idx = blockIdx.x * blockDim.x + threadIdx.x;
    if (idx >= BS * CH * HW) return;
    int b = idx / (CH * HW);
    int pos = idx % HW;
    out[idx] = fqin[idx] * nrm[b * HW + pos] + att[idx] * nrm[(BS + b) * HW + pos] * 0.5f;
}

// ---------------- launch ----------------
extern "C" void kernel_launch(void* const* d_in, const int* in_sizes, int n_in,
                              void* d_out, int out_size) {
    const float* fqf = (const float*)d_in[0];
    const float* fsf = (const float*)d_in[1];
    const float* f_q = (const float*)d_in[2];
    const float* f_s = (const float*)d_in[3];
    const float* w1  = (const float*)d_in[4];
    const float* w2  = (const float*)d_in[5];
    const float* w3  = (const float*)d_in[6];
    float* out = (float*)d_out;

    float *part, *invn, *corrP, *corrI, *buf1, *buf2, *c4ab, *c4, *attn, *nrm;
    int* cnt;
    u64 *wd1, *wd2, *wd3;
    cudaGetSymbolAddress((void**)&part,  g_part);
    cudaGetSymbolAddress((void**)&cnt,   g_cnt);
    cudaGetSymbolAddress((void**)&invn,  g_invn);
    cudaGetSymbolAddress((void**)&corrP, g_corrP);
    cudaGetSymbolAddress((void**)&corrI, g_corrI);
    cudaGetSymbolAddress((void**)&buf1,  g_buf1I);
    cudaGetSymbolAddress((void**)&buf2,  g_buf2I);
    cudaGetSymbolAddress((void**)&c4ab,  g_c4abI);
    cudaGetSymbolAddress((void**)&c4,    g_c4);
    cudaGetSymbolAddress((void**)&attn,  g_attn);
    cudaGetSymbolAddress((void**)&nrm,   g_nrm);
    cudaGetSymbolAddress((void**)&wd1,   g_wd1);
    cudaGetSymbolAddress((void**)&wd2,   g_wd2);
    cudaGetSymbolAddress((void**)&wd3,   g_wd3);

    // 1. prep: full-chip sumsq + last-block reduce + weight dup
    prep_k<<<dim3(NLB, 2, 8), 400>>>(fqf, fsf, part, cnt, invn, w1, w2, w3, wd1, wd2, wd3);

    // 2. correlation tensor (K-split 2, raw partials, 2 blocks/SM)
    corr_gemm_k<<<dim3(2, 4, 2 * NLB), 400>>>(fqf, fsf, corrP);

    // 3. branch-interleave + partial-sum + norm scaling
    transI_k<<<dim3(13, 13, NLB), dim3(32, 8)>>>(corrP, invn, corrI);

    // 4. neighborhood consensus (launch #4 = conv1 -> ncu capture; R11 config)
    conv4d_k<9, 10, 2, 5, 2, 200, 3><<<BS * HW, 200>>>(corrI, wd1, buf1);
    conv4d_k<10, 10, 2, 5, 2, 200, 3><<<BS * HW, 200>>>(buf1, wd2, buf2);
    conv4d_k<10, 1, 1, 2, 2, 100, 4><<<BS * HW, 100>>>(buf2, wd3, c4ab);

    // 5. combine branches
    addt2_k<<<dim3(13, 13, BS), dim3(32, 8)>>>(c4ab, c4);

    // 6. softmax + attention
    softmax_k<<<BS * HW, 128>>>(c4, attn);
    attn_gemm_k<<<dim3(7, 4, BS), 256>>>(attn, f_s, out + BS * CH * HW);

    // 7. final L2-norm combine
    norm2_k<<<dim3(BS, 2), 400>>>(f_q, out + BS * CH * HW, nrm);
    combine_k<<<(BS * CH * HW + 255) / 256, 256>>>(f_q, out + BS * CH * HW, nrm, out);
}

// round 15
// speedup vs baseline: 1.0651x; 1.0299x over previous
#include <cuda_runtime.h>
#include <math.h>
#include <stdint.h>

#define HW   400
#define LCH  9
#define BS   2
#define CD   1024
#define CH   256
#define NLB  18
#define TEMP 20.0f

typedef unsigned long long u64;

// ---------------- scratch ----------------
__device__ float g_part [2 * NLB * 8 * HW];                 // partial sums
__device__ int   g_cnt  [2 * NLB];                          // arrival counters (self-reset)
__device__ float g_invn [2 * NLB * HW];
__device__ float g_corr [(size_t)NLB * HW * HW];
__device__ float g_corrI[(size_t)NLB * HW * HW * 2];        // (corr, corrT) interleaved
__device__ float g_buf1I[(size_t)BS * 10 * HW * HW * 2];
__device__ float g_buf2I[(size_t)BS * 10 * HW * HW * 2];
__device__ float g_c4abI[(size_t)BS * HW * HW * 2];
__device__ float g_c4   [BS * HW * HW];
__device__ float g_attn [BS * HW * HW];
__device__ float g_nrm  [2 * BS * HW];
__device__ u64   g_wd1  [9 * 81 * 10];                      // (w,w) dup weights
__device__ u64   g_wd2  [10 * 81 * 10];
__device__ u64   g_wd3  [10 * 81 * 1];

// ---------------- f32x2 helpers ----------------
__device__ __forceinline__ u64 pack2(float x, float y) {
    u64 r;
    asm("mov.b64 %0, {%1, %2};" : "=l"(r) : "f"(x), "f"(y));
    return r;
}
__device__ __forceinline__ void unpack2(u64 v, float& x, float& y) {
    asm("mov.b64 {%0, %1}, %2;" : "=f"(x), "=f"(y) : "l"(v));
}
__device__ __forceinline__ void fma2(u64& d, u64 a, u64 b) {
    asm("fma.rn.f32x2 %0, %1, %2, %0;" : "+l"(d) : "l"(a), "l"(b));
}

// ---------------- prep: full-chip partial sumsq + last-block reduce + weight dup ----------------
__global__ void prep_k(const float* __restrict__ fq, const float* __restrict__ fs,
                       float* __restrict__ part, int* __restrict__ cnt,
                       float* __restrict__ inv,
                       const float* __restrict__ w1, const float* __restrict__ w2,
                       const float* __restrict__ w3,
                       u64* __restrict__ o1, u64* __restrict__ o2, u64* __restrict__ o3) {
    int z = blockIdx.y, lb = blockIdx.x, ch = blockIdx.z;
    int pos = threadIdx.x;
    const float* x = (z ? fs : fq) + ((size_t)lb * CD + ch * 128) * HW + pos;
    float s0 = 0.f, s1 = 0.f, s2 = 0.f, s3 = 0.f;
    #pragma unroll 4
    for (int c = 0; c < 128; c += 4) {
        float v0 = x[(size_t)(c + 0) * HW];
        float v1 = x[(size_t)(c + 1) * HW];
        float v2 = x[(size_t)(c + 2) * HW];
        float v3 = x[(size_t)(c + 3) * HW];
        s0 += v0 * v0; s1 += v1 * v1; s2 += v2 * v2; s3 += v3 * v3;
    }
    part[(((size_t)z * NLB + lb) * 8 + ch) * HW + pos] = (s0 + s1) + (s2 + s3);

    if (z == 0 && lb == 0 && ch == 0) {
        for (int idx = pos; idx < 10 * 81 * 10; idx += 400) {
            if (idx < 9 * 81 * 10) {
                int co = idx % 10, rem = idx / 10;
                int ci = rem / 81, tap = rem % 81;
                float w = w1[((size_t)co * 9 + ci) * 81 + tap];
                o1[idx] = pack2(w, w);
            }
            {
                int co = idx % 10, rem = idx / 10;
                int ci = rem / 81, tap = rem % 81;
                float w = w2[((size_t)co * 10 + ci) * 81 + tap];
                o2[idx] = pack2(w, w);
            }
            if (idx < 10 * 81) {
                float w = w3[idx];
                o3[idx] = pack2(w, w);
            }
        }
    }

    __threadfence();
    __syncthreads();
    __shared__ int lastflag;
    if (pos == 0) lastflag = (atomicAdd(&cnt[z * NLB + lb], 1) == 7) ? 1 : 0;
    __syncthreads();
    if (lastflag) {
        const float* p = part + ((size_t)z * NLB + lb) * 8 * HW + pos;
        float s = 0.f;
        #pragma unroll
        for (int c = 0; c < 8; c++) s += p[c * HW];
        inv[z * NLB * HW + lb * HW + pos] = 1.f / fmaxf(sqrtf(s), 1e-12f);
        if (pos == 0) cnt[z * NLB + lb] = 0;
    }
}

// ---------------- correlation GEMM (TN), FFMA2 + register prefetch (R4 config) ----------------
__global__ void __launch_bounds__(400) corr_gemm_k(
        const float* __restrict__ fq, const float* __restrict__ fs,
        const float* __restrict__ invn, float* __restrict__ corr) {
    int lb = blockIdx.z;
    const float* A  = fq + (size_t)lb * CD * HW;
    const float* Bm = fs + (size_t)lb * CD * HW;
    int ij0 = blockIdx.y * 100, km0 = blockIdx.x * 200;

    __shared__ float As[16][100];
    __shared__ float Bs[16][200];
    int tid = threadIdx.x;
    int tx = tid % 20, ty = tid / 20;

    u64 acc[5][5];
    #pragma unroll
    for (int r = 0; r < 5; r++)
        #pragma unroll
        for (int s = 0; s < 5; s++) acc[r][s] = 0ull;

    int ka = tid / 25,  va = (tid % 25) * 4;
    int kb0 = tid / 50, vb0 = (tid % 50) * 4;
    int kb1 = (tid + 400) / 50, vb1 = ((tid + 400) % 50) * 4;
    const float* Ap  = A  + (size_t)ka  * HW + ij0 + va;
    const float* Bp0 = Bm + (size_t)kb0 * HW + km0 + vb0;
    const float* Bp1 = Bm + (size_t)kb1 * HW + km0 + vb1;

    float4 pa  = *(const float4*)Ap;
    float4 pb0 = *(const float4*)Bp0;
    float4 pb1 = *(const float4*)Bp1;

    for (int c0 = 0; c0 < CD; c0 += 16) {
        *(float4*)&As[ka][va]   = pa;
        *(float4*)&Bs[kb0][vb0] = pb0;
        *(float4*)&Bs[kb1][vb1] = pb1;
        __syncthreads();
        if (c0 + 16 < CD) {
            pa  = *(const float4*)(Ap  + (size_t)(c0 + 16) * HW);
            pb0 = *(const float4*)(Bp0 + (size_t)(c0 + 16) * HW);
            pb1 = *(const float4*)(Bp1 + (size_t)(c0 + 16) * HW);
        }
        #pragma unroll
        for (int kk = 0; kk < 16; kk++) {
            u64 a[5], b[5];
            #pragma unroll
            for (int r = 0; r < 5; r++) {
                float av = As[kk][r * 20 + ty];
                a[r] = pack2(av, av);
            }
            #pragma unroll
            for (int s = 0; s < 5; s++)
                b[s] = *(const u64*)&Bs[kk][tx * 10 + 2 * s];
            #pragma unroll
            for (int r = 0; r < 5; r++)
                #pragma unroll
                for (int s = 0; s < 5; s++) fma2(acc[r][s], a[r], b[s]);
        }
        __syncthreads();
    }

    int b = lb & 1, l = lb >> 1;
    const float* iq = invn + (size_t)lb * HW;
    const float* is = invn + NLB * HW + (size_t)lb * HW;
    float* cp = corr + (size_t)(b * LCH + l) * HW * HW;
    #pragma unroll
    for (int r = 0; r < 5; r++) {
        int ij = ij0 + r * 20 + ty;
        float sq = iq[ij];
        #pragma unroll
        for (int s = 0; s < 5; s++) {
            int col = km0 + tx * 10 + 2 * s;
            float2 isv = *(const float2*)&is[col];
            float lo, hi;
            unpack2(acc[r][s], lo, hi);
            float2 o;
            o.x = lo * sq * isv.x;
            o.y = hi * sq * isv.y;
            *(float2*)&cp[(size_t)ij * HW + col] = o;
        }
    }
}

// ---------------- interleave: out[ij][km] = (A[ij][km], A[km][ij]) ----------------
__global__ void transI_k(const float* __restrict__ in, float* __restrict__ out) {
    __shared__ float t1[32][33];
    __shared__ float t2[32][33];
    int mtx = blockIdx.z;
    const float* A = in + (size_t)mtx * HW * HW;
    float* O = out + (size_t)mtx * HW * HW * 2;
    int x0 = blockIdx.x * 32, y0 = blockIdx.y * 32;
    int tx = threadIdx.x, ty = threadIdx.y;
    #pragma unroll
    for (int r = 0; r < 32; r += 8) {
        int yy = y0 + ty + r, xx = x0 + tx;
        t1[ty + r][tx] = (yy < HW && xx < HW) ? A[(size_t)yy * HW + xx] : 0.f;
        int y2 = x0 + ty + r, x2 = y0 + tx;
        t2[ty + r][tx] = (y2 < HW && x2 < HW) ? A[(size_t)y2 * HW + x2] : 0.f;
    }
    __syncthreads();
    #pragma unroll
    for (int r = 0; r < 32; r += 8) {
        int ij = y0 + ty + r, km = x0 + tx;
        if (ij < HW && km < HW) {
            float2 o;
            o.x = t1[ty + r][tx];
            o.y = t2[tx][ty + r];
            *(float2*)&O[((size_t)ij * HW + km) * 2] = o;
        }
    }
}

// ---------------- 4D conv (3x3x3x3, pad 1, relu), branch-pair FFMA2 (R11 config) ----------
template <int CIN, int COUT, int CO2, int PK, int PM, int NT, int MAXB>
__global__ void __launch_bounds__(NT, MAXB) conv4d_k(
        const float* __restrict__ x, const u64* __restrict__ wd,
        float* __restrict__ y) {
    constexpr int NPK = 20 / PK, NPM = 20 / PM;
    constexpr int NPATCH = NPK * NPM;
    constexpr int NSTG = 200 / NT;

    __shared__ u64 sp2[9 * 484];
    __shared__ u64 wc2[81 * COUT];

    int bij = blockIdx.x;
    int bb = bij / HW, ij = bij % HW;
    int i = ij / 20, j = ij % 20;
    int tid = threadIdx.x;
    int cobase = (tid / NPATCH) * CO2;
    int pid = tid % NPATCH;
    int k0 = (pid / NPM) * PK;
    int m0 = (pid % NPM) * PM;

    for (int t = tid; t < 9 * 484; t += NT) sp2[t] = 0ull;

    bool pok[9];
    int  po[9];
    #pragma unroll
    for (int p = 0; p < 9; p++) {
        int di = p / 3, dj = p % 3;
        int ii = i + di - 1, jj = j + dj - 1;
        pok[p] = ((unsigned)ii < 20u) && ((unsigned)jj < 20u);
        po[p]  = (ii * 20 + jj) * 800;
    }
    int  soff[NSTG];
    int  doff[NSTG];
    #pragma unroll
    for (int q = 0; q < NSTG; q++) {
        int rem2 = tid + q * NT;
        int r = rem2 / 10, c2 = (rem2 % 10) * 2;
        soff[q] = (r * 20 + c2) * 2;
        doff[q] = (r + 1) * 22 + (c2 + 1);
    }

    u64 acc[CO2][PK][PM];
    #pragma unroll
    for (int c = 0; c < CO2; c++)
        #pragma unroll
        for (int pk = 0; pk < PK; pk++)
            #pragma unroll
            for (int pm = 0; pm < PM; pm++) acc[c][pk][pm] = 0ull;

    const float* xb = x + (size_t)bb * CIN * 320000;

    for (int ci = 0; ci < CIN; ci++) {
        __syncthreads();
        for (int t = tid; t < 81 * COUT; t += NT)
            wc2[t] = wd[(size_t)ci * 81 * COUT + t];
        const float* xci = xb + (size_t)ci * 320000;
        #pragma unroll
        for (int p = 0; p < 9; p++) {
            #pragma unroll
            for (int q = 0; q < NSTG; q++) {
                ulonglong2 v = make_ulonglong2(0ull, 0ull);
                if (pok[p]) v = *(const ulonglong2*)(xci + po[p] + soff[q]);
                u64* dst = &sp2[p * 484 + doff[q]];
                dst[0] = v.x;
                dst[1] = v.y;
            }
        }
        __syncthreads();

        #pragma unroll
        for (int dij = 0; dij < 9; dij++) {
            const u64* P = sp2 + dij * 484 + k0 * 22 + m0;
            u64 w2[CO2][9];
            #pragma unroll
            for (int t = 0; t < 9; t++) {
                if (CO2 == 2) {
                    ulonglong2 wv = *(const ulonglong2*)&wc2[(dij * 9 + t) * COUT + cobase];
                    w2[0][t] = wv.x;
                    w2[CO2 - 1][t] = wv.y;
                } else {
                    w2[0][t] = wc2[(dij * 9 + t) * COUT + cobase];
                }
            }
            #pragma unroll
            for (int r = 0; r < PK + 2; r++) {
                u64 xr[PM + 2];
                #pragma unroll
                for (int h = 0; h < (PM + 2) / 2; h++) {
                    ulonglong2 v = *(const ulonglong2*)&P[r * 22 + 2 * h];
                    xr[2 * h] = v.x;
                    xr[2 * h + 1] = v.y;
                }
                #pragma unroll
                for (int dk = 0; dk < 3; dk++) {
                    int pk = r - dk;
                    if (pk < 0 || pk >= PK) continue;
                    #pragma unroll
                    for (int dm = 0; dm < 3; dm++)
                        #pragma unroll
                        for (int c = 0; c < CO2; c++)
                            #pragma unroll
                            for (int pm = 0; pm < PM; pm++)
                                fma2(acc[c][pk][pm], xr[pm + dm], w2[c][dk * 3 + dm]);
                }
            }
        }
    }

    #pragma unroll
    for (int c = 0; c < CO2; c++) {
        float* yp = y + (((size_t)(bb * COUT + cobase + c) * 400 + ij) * 400) * 2;
        #pragma unroll
        for (int pk = 0; pk < PK; pk++)
            #pragma unroll
            for (int pm = 0; pm < PM; pm++) {
                float lo, hi;
                unpack2(acc[c][pk][pm], lo, hi);
                float2 o;
                o.x = fmaxf(lo, 0.f);
                o.y = fmaxf(hi, 0.f);
                *(float2*)&yp[((k0 + pk) * 20 + m0 + pm) * 2] = o;
            }
    }
}

// ---------------- combine branches: c4[q][s] = I[q][s].x + I[s][q].y ----------------
__global__ void addt2_k(const float* __restrict__ I, float* __restrict__ o) {
    __shared__ float t1[32][33];
    __shared__ float t2[32][33];
    int b = blockIdx.z;
    const float* Ib = I + (size_t)b * HW * HW * 2;
    float* O = o + (size_t)b * HW * HW;
    int q0 = blockIdx.y * 32, s0 = blockIdx.x * 32;
    int tx = threadIdx.x, ty = threadIdx.y;
    #pragma unroll
    for (int r = 0; r < 32; r += 8) {
        int q = q0 + ty + r, s = s0 + tx;
        t1[ty + r][tx] = (q < HW && s < HW) ? Ib[((size_t)q * HW + s) * 2] : 0.f;
        int s2 = s0 + ty + r, q2 = q0 + tx;
        t2[ty + r][tx] = (s2 < HW && q2 < HW) ? Ib[((size_t)s2 * HW + q2) * 2 + 1] : 0.f;
    }
    __syncthreads();
    #pragma unroll
    for (int r = 0; r < 32; r += 8) {
        int q = q0 + ty + r, s = s0 + tx;
        if (q < HW && s < HW) O[(size_t)q * HW + s] = t1[ty + r][tx] + t2[tx][ty + r];
    }
}

// ---------------- softmax ----------------
__global__ void softmax_k(const float* __restrict__ x, float* __restrict__ y) {
    int row = blockIdx.x;
    const float* xr = x + (size_t)row * HW;
    float*       yr = y + (size_t)row * HW;
    __shared__ float sh[HW];
    __shared__ float red[4];
    int tid = threadIdx.x;
    float mx = -3.4e38f;
    for (int i = tid; i < HW; i += 128) {
        float v = xr[i] * TEMP;
        sh[i] = v;
        mx = fmaxf(mx, v);
    }
    #pragma unroll
    for (int o = 16; o; o >>= 1) mx = fmaxf(mx, __shfl_xor_sync(0xffffffffu, mx, o));
    if ((tid & 31) == 0) red[tid >> 5] = mx;
    __syncthreads();
    mx = fmaxf(fmaxf(red[0], red[1]), fmaxf(red[2], red[3]));
    float sum = 0.f;
    for (int i = tid; i < HW; i += 128) {
        float e = expf(sh[i] - mx);
        sh[i] = e;
        sum += e;
    }
    #pragma unroll
    for (int o = 16; o; o >>= 1) sum += __shfl_xor_sync(0xffffffffu, sum, o);
    __syncthreads();
    if ((tid & 31) == 0) red[tid >> 5] = sum;
    __syncthreads();
    float inv = 1.f / (red[0] + red[1] + red[2] + red[3]);
    for (int i = tid; i < HW; i += 128) yr[i] = sh[i] * inv;
}

// ---------------- attention GEMM (NT) ----------------
__global__ void attn_gemm_k(const float* __restrict__ attn, const float* __restrict__ v,
                            float* __restrict__ out) {
    int b = blockIdx.z;
    const float* A = v    + (size_t)b * CH * HW;
    const float* P = attn + (size_t)b * HW * HW;
    int c0 = blockIdx.y * 64, q0 = blockIdx.x * 64;

    __shared__ float As[16][65];
    __shared__ float Ps[16][65];
    int tid = threadIdx.x;
    int tx = tid & 15, ty = tid >> 4;
    float acc[4][4] = {};

    for (int s0 = 0; s0 < HW; s0 += 16) {
        #pragma unroll
        for (int t = tid; t < 1024; t += 256) {
            int row = t >> 4, kk = t & 15;
            int c = c0 + row, q = q0 + row;
            As[kk][row] = (c < CH) ? A[(size_t)c * HW + s0 + kk] : 0.f;
            Ps[kk][row] = (q < HW) ? P[(size_t)q * HW + s0 + kk] : 0.f;
        }
        __syncthreads();
        #pragma unroll
        for (int kk = 0; kk < 16; kk++) {
            float a[4], p[4];
            #pragma unroll
            for (int r = 0; r < 4; r++) { a[r] = As[kk][ty * 4 + r]; p[r] = Ps[kk][tx * 4 + r]; }
            #pragma unroll
            for (int r = 0; r < 4; r++)
                #pragma unroll
                for (int s = 0; s < 4; s++) acc[r][s] += a[r] * p[s];
        }
        __syncthreads();
    }
    #pragma unroll
    for (int r = 0; r < 4; r++) {
        int c = c0 + ty * 4 + r;
        if (c >= CH) continue;
        #pragma unroll
        for (int s = 0; s < 4; s++) {
            int q = q0 + tx * 4 + s;
            if (q < HW) out[((size_t)b * CH + c) * HW + q] = acc[r][s];
        }
    }
}

// ---------------- final norms + combine ----------------
__global__ void norm2_k(const float* __restrict__ fqin, const float* __restrict__ att,
                        float* __restrict__ nrm) {
    int b = blockIdx.x, z = blockIdx.y;
    const float* x = (z ? att : fqin) + (size_t)b * CH * HW + threadIdx.x;
    float s0 = 0.f, s1 = 0.f, s2 = 0.f, s3 = 0.f;
    #pragma unroll 4
    for (int c = 0; c < CH; c += 4) {      // 4 independent chains -> MLP 4
        float v0 = x[(size_t)(c + 0) * HW];
        float v1 = x[(size_t)(c + 1) * HW];
        float v2 = x[(size_t)(c + 2) * HW];
        float v3 = x[(size_t)(c + 3) * HW];
        s0 += v0 * v0; s1 += v1 * v1; s2 += v2 * v2; s3 += v3 * v3;
    }
    float s = (s0 + s1) + (s2 + s3);
    nrm[(z * BS + b) * HW + threadIdx.x] = 1.f / fmaxf(sqrtf(s), 1e-12f);
}

__global__ void combine_k(const float* __restrict__ fqin, const float* __restrict__ att,
                          const float* __restrict__ nrm, float* __restrict__ out) {
    int idx = blockIdx.x * blockDim.x + threadIdx.x;
    if (idx >= BS * CH * HW) return;
    int b = idx / (CH * HW);
    int pos = idx % HW;
    out[idx] = fqin[idx] * nrm[b * HW + pos] + att[idx] * nrm[(BS + b) * HW + pos] * 0.5f;
}

// ---------------- launch ----------------
extern "C" void kernel_launch(void* const* d_in, const int* in_sizes, int n_in,
                              void* d_out, int out_size) {
    const float* fqf = (const float*)d_in[0];
    const float* fsf = (const float*)d_in[1];
    const float* f_q = (const float*)d_in[2];
    const float* f_s = (const float*)d_in[3];
    const float* w1  = (const float*)d_in[4];
    const float* w2  = (const float*)d_in[5];
    const float* w3  = (const float*)d_in[6];
    float* out = (float*)d_out;

    float *part, *invn, *corr, *corrI, *buf1, *buf2, *c4ab, *c4, *attn, *nrm;
    int* cnt;
    u64 *wd1, *wd2, *wd3;
    cudaGetSymbolAddress((void**)&part,  g_part);
    cudaGetSymbolAddress((void**)&cnt,   g_cnt);
    cudaGetSymbolAddress((void**)&invn,  g_invn);
    cudaGetSymbolAddress((void**)&corr,  g_corr);
    cudaGetSymbolAddress((void**)&corrI, g_corrI);
    cudaGetSymbolAddress((void**)&buf1,  g_buf1I);
    cudaGetSymbolAddress((void**)&buf2,  g_buf2I);
    cudaGetSymbolAddress((void**)&c4ab,  g_c4abI);
    cudaGetSymbolAddress((void**)&c4,    g_c4);
    cudaGetSymbolAddress((void**)&attn,  g_attn);
    cudaGetSymbolAddress((void**)&nrm,   g_nrm);
    cudaGetSymbolAddress((void**)&wd1,   g_wd1);
    cudaGetSymbolAddress((void**)&wd2,   g_wd2);
    cudaGetSymbolAddress((void**)&wd3,   g_wd3);

    // 1. prep: full-chip sumsq + last-block reduce + weight dup
    prep_k<<<dim3(NLB, 2, 8), 400>>>(fqf, fsf, part, cnt, invn, w1, w2, w3, wd1, wd2, wd3);

    // 2. correlation tensor (R4 config, 202us measured)
    corr_gemm_k<<<dim3(2, 4, NLB), 400>>>(fqf, fsf, invn, corr);

    // 3. branch-interleave
    transI_k<<<dim3(13, 13, NLB), dim3(32, 8)>>>(corr, corrI);

    // 4. neighborhood consensus (launch #4 = conv1 -> ncu capture; R11 config)
    conv4d_k<9, 10, 2, 5, 2, 200, 3><<<BS * HW, 200>>>(corrI, wd1, buf1);
    conv4d_k<10, 10, 2, 5, 2, 200, 3><<<BS * HW, 200>>>(buf1, wd2, buf2);
    conv4d_k<10, 1, 1, 2, 2, 100, 4><<<BS * HW, 100>>>(buf2, wd3, c4ab);

    // 5. combine branches
    addt2_k<<<dim3(13, 13, BS), dim3(32, 8)>>>(c4ab, c4);

    // 6. softmax + attention
    softmax_k<<<BS * HW, 128>>>(c4, attn);
    attn_gemm_k<<<dim3(7, 4, BS), 256>>>(attn, f_s, out + BS * CH * HW);

    // 7. final L2-norm combine
    norm2_k<<<dim3(BS, 2), 400>>>(f_q, out + BS * CH * HW, nrm);
    combine_k<<<(BS * CH * HW + 255) / 256, 256>>>(f_q, out + BS * CH * HW, nrm, out);
}

// round 16
// speedup vs baseline: 1.2308x; 1.1556x over previous
#include <cuda_runtime.h>
#include <math.h>
#include <stdint.h>

#define HW   400
#define LCH  9
#define BS   2
#define CD   1024
#define CH   256
#define NLB  18
#define TEMP 20.0f

typedef unsigned long long u64;

// ---------------- scratch ----------------
__device__ float g_part [2 * NLB * 8 * HW];
__device__ int   g_cnt  [2 * NLB];
__device__ float g_invn [2 * NLB * HW];
__device__ float g_corr [(size_t)NLB * HW * HW];
__device__ float g_corrI[(size_t)NLB * HW * HW * 2];
__device__ float g_buf1I[(size_t)BS * 10 * HW * HW * 2];
__device__ float g_buf2I[(size_t)BS * 10 * HW * HW * 2];
__device__ float g_c4abI[(size_t)BS * HW * HW * 2];
__device__ float g_c4   [BS * HW * HW];
__device__ float g_attn [BS * HW * HW];
__device__ float g_nrm  [2 * BS * HW];
__device__ u64   g_wd1  [9 * 81 * 10];
__device__ u64   g_wd2  [10 * 81 * 10];
__device__ u64   g_wd3  [10 * 81 * 1];

// ---------------- f32x2 helpers ----------------
__device__ __forceinline__ u64 pack2(float x, float y) {
    u64 r;
    asm("mov.b64 %0, {%1, %2};" : "=l"(r) : "f"(x), "f"(y));
    return r;
}
__device__ __forceinline__ void unpack2(u64 v, float& x, float& y) {
    asm("mov.b64 {%0, %1}, %2;" : "=f"(x), "=f"(y) : "l"(v));
}
__device__ __forceinline__ void fma2(u64& d, u64 a, u64 b) {
    asm("fma.rn.f32x2 %0, %1, %2, %0;" : "+l"(d) : "l"(a), "l"(b));
}

// ---------------- prep ----------------
__global__ void prep_k(const float* __restrict__ fq, const float* __restrict__ fs,
                       float* __restrict__ part, int* __restrict__ cnt,
                       float* __restrict__ inv,
                       const float* __restrict__ w1, const float* __restrict__ w2,
                       const float* __restrict__ w3,
                       u64* __restrict__ o1, u64* __restrict__ o2, u64* __restrict__ o3) {
    int z = blockIdx.y, lb = blockIdx.x, ch = blockIdx.z;
    int pos = threadIdx.x;
    const float* x = (z ? fs : fq) + ((size_t)lb * CD + ch * 128) * HW + pos;
    float s0 = 0.f, s1 = 0.f, s2 = 0.f, s3 = 0.f;
    #pragma unroll 4
    for (int c = 0; c < 128; c += 4) {
        float v0 = x[(size_t)(c + 0) * HW];
        float v1 = x[(size_t)(c + 1) * HW];
        float v2 = x[(size_t)(c + 2) * HW];
        float v3 = x[(size_t)(c + 3) * HW];
        s0 += v0 * v0; s1 += v1 * v1; s2 += v2 * v2; s3 += v3 * v3;
    }
    part[(((size_t)z * NLB + lb) * 8 + ch) * HW + pos] = (s0 + s1) + (s2 + s3);

    if (z == 0 && lb == 0 && ch == 0) {
        for (int idx = pos; idx < 10 * 81 * 10; idx += 400) {
            if (idx < 9 * 81 * 10) {
                int co = idx % 10, rem = idx / 10;
                int ci = rem / 81, tap = rem % 81;
                float w = w1[((size_t)co * 9 + ci) * 81 + tap];
                o1[idx] = pack2(w, w);
            }
            {
                int co = idx % 10, rem = idx / 10;
                int ci = rem / 81, tap = rem % 81;
                float w = w2[((size_t)co * 10 + ci) * 81 + tap];
                o2[idx] = pack2(w, w);
            }
            if (idx < 10 * 81) {
                float w = w3[idx];
                o3[idx] = pack2(w, w);
            }
        }
    }

    __threadfence();
    __syncthreads();
    __shared__ int lastflag;
    if (pos == 0) lastflag = (atomicAdd(&cnt[z * NLB + lb], 1) == 7) ? 1 : 0;
    __syncthreads();
    if (lastflag) {
        const float* p = part + ((size_t)z * NLB + lb) * 8 * HW + pos;
        float s = 0.f;
        #pragma unroll
        for (int c = 0; c < 8; c++) s += p[c * HW];
        inv[z * NLB * HW + lb * HW + pos] = 1.f / fmaxf(sqrtf(s), 1e-12f);
        if (pos == 0) cnt[z * NLB + lb] = 0;
    }
}

// ---------------- correlation GEMM (TN), FFMA2 + register prefetch (R4 config) ----------------
__global__ void __launch_bounds__(400) corr_gemm_k(
        const float* __restrict__ fq, const float* __restrict__ fs,
        const float* __restrict__ invn, float* __restrict__ corr) {
    int lb = blockIdx.z;
    const float* A  = fq + (size_t)lb * CD * HW;
    const float* Bm = fs + (size_t)lb * CD * HW;
    int ij0 = blockIdx.y * 100, km0 = blockIdx.x * 200;

    __shared__ float As[16][100];
    __shared__ float Bs[16][200];
    int tid = threadIdx.x;
    int tx = tid % 20, ty = tid / 20;

    u64 acc[5][5];
    #pragma unroll
    for (int r = 0; r < 5; r++)
        #pragma unroll
        for (int s = 0; s < 5; s++) acc[r][s] = 0ull;

    int ka = tid / 25,  va = (tid % 25) * 4;
    int kb0 = tid / 50, vb0 = (tid % 50) * 4;
    int kb1 = (tid + 400) / 50, vb1 = ((tid + 400) % 50) * 4;
    const float* Ap  = A  + (size_t)ka  * HW + ij0 + va;
    const float* Bp0 = Bm + (size_t)kb0 * HW + km0 + vb0;
    const float* Bp1 = Bm + (size_t)kb1 * HW + km0 + vb1;

    float4 pa  = *(const float4*)Ap;
    float4 pb0 = *(const float4*)Bp0;
    float4 pb1 = *(const float4*)Bp1;

    for (int c0 = 0; c0 < CD; c0 += 16) {
        *(float4*)&As[ka][va]   = pa;
        *(float4*)&Bs[kb0][vb0] = pb0;
        *(float4*)&Bs[kb1][vb1] = pb1;
        __syncthreads();
        if (c0 + 16 < CD) {
            pa  = *(const float4*)(Ap  + (size_t)(c0 + 16) * HW);
            pb0 = *(const float4*)(Bp0 + (size_t)(c0 + 16) * HW);
            pb1 = *(const float4*)(Bp1 + (size_t)(c0 + 16) * HW);
        }
        #pragma unroll
        for (int kk = 0; kk < 16; kk++) {
            u64 a[5], b[5];
            #pragma unroll
            for (int r = 0; r < 5; r++) {
                float av = As[kk][r * 20 + ty];
                a[r] = pack2(av, av);
            }
            #pragma unroll
            for (int s = 0; s < 5; s++)
                b[s] = *(const u64*)&Bs[kk][tx * 10 + 2 * s];
            #pragma unroll
            for (int r = 0; r < 5; r++)
                #pragma unroll
                for (int s = 0; s < 5; s++) fma2(acc[r][s], a[r], b[s]);
        }
        __syncthreads();
    }

    int b = lb & 1, l = lb >> 1;
    const float* iq = invn + (size_t)lb * HW;
    const float* is = invn + NLB * HW + (size_t)lb * HW;
    float* cp = corr + (size_t)(b * LCH + l) * HW * HW;
    #pragma unroll
    for (int r = 0; r < 5; r++) {
        int ij = ij0 + r * 20 + ty;
        float sq = iq[ij];
        #pragma unroll
        for (int s = 0; s < 5; s++) {
            int col = km0 + tx * 10 + 2 * s;
            float2 isv = *(const float2*)&is[col];
            float lo, hi;
            unpack2(acc[r][s], lo, hi);
            float2 o;
            o.x = lo * sq * isv.x;
            o.y = hi * sq * isv.y;
            *(float2*)&cp[(size_t)ij * HW + col] = o;
        }
    }
}

// ---------------- interleave: out[ij][km] = (A[ij][km], A[km][ij]) ----------------
__global__ void transI_k(const float* __restrict__ in, float* __restrict__ out) {
    __shared__ float t1[32][33];
    __shared__ float t2[32][33];
    int mtx = blockIdx.z;
    const float* A = in + (size_t)mtx * HW * HW;
    float* O = out + (size_t)mtx * HW * HW * 2;
    int x0 = blockIdx.x * 32, y0 = blockIdx.y * 32;
    int tx = threadIdx.x, ty = threadIdx.y;
    #pragma unroll
    for (int r = 0; r < 32; r += 8) {
        int yy = y0 + ty + r, xx = x0 + tx;
        t1[ty + r][tx] = (yy < HW && xx < HW) ? A[(size_t)yy * HW + xx] : 0.f;
        int y2 = x0 + ty + r, x2 = y0 + tx;
        t2[ty + r][tx] = (y2 < HW && x2 < HW) ? A[(size_t)y2 * HW + x2] : 0.f;
    }
    __syncthreads();
    #pragma unroll
    for (int r = 0; r < 32; r += 8) {
        int ij = y0 + ty + r, km = x0 + tx;
        if (ij < HW && km < HW) {
            float2 o;
            o.x = t1[ty + r][tx];
            o.y = t2[tx][ty + r];
            *(float2*)&O[((size_t)ij * HW + km) * 2] = o;
        }
    }
}

// ---------------- 4D conv, generic-NT variant (conv1/conv2): CO2 co, PKxPM patch --------
// Staging decomposition precomputed per thread (works for any NT).
template <int CIN, int COUT, int CO2, int PK, int PM, int NT, int MAXB>
__global__ void __launch_bounds__(NT, MAXB) conv4d_g_k(
        const float* __restrict__ x, const u64* __restrict__ wd,
        float* __restrict__ y) {
    constexpr int NPM = 20 / PM;
    constexpr int NPATCH = (20 / PK) * NPM;
    constexpr int NSTG = (9 * 200 + NT - 1) / NT;
    constexpr int WTOT = 81 * COUT;

    __shared__ u64 sp2[9 * 484];
    __shared__ u64 wc2[WTOT];

    int bij = blockIdx.x;
    int bb = bij / HW, ij = bij % HW;
    int i = ij / 20, j = ij % 20;
    int tid = threadIdx.x;
    int cobase = (tid / NPATCH) * CO2;
    int pid = tid % NPATCH;
    int k0 = (pid / NPM) * PK;
    int m0 = (pid % NPM) * PM;

    for (int t = tid; t < 9 * 484; t += NT) sp2[t] = 0ull;

    // hoisted staging tables
    int  srcoff[NSTG];
    int  dstoff[NSTG];
    bool okq[NSTG];
    bool valq[NSTG];
    #pragma unroll
    for (int q = 0; q < NSTG; q++) {
        int t = tid + q * NT;
        valq[q] = (t < 9 * 200);
        int tt = valq[q] ? t : 0;
        int p = tt / 200, rem2 = tt % 200;
        int di = p / 3, dj = p % 3;
        int ii = i + di - 1, jj = j + dj - 1;
        okq[q] = ((unsigned)ii < 20u) && ((unsigned)jj < 20u);
        int r = rem2 / 10, c2 = (rem2 % 10) * 2;
        srcoff[q] = (ii * 20 + jj) * 800 + (r * 20 + c2) * 2;
        dstoff[q] = p * 484 + (r + 1) * 22 + (c2 + 1);
    }

    u64 acc[CO2][PK][PM];
    #pragma unroll
    for (int c = 0; c < CO2; c++)
        #pragma unroll
        for (int pk = 0; pk < PK; pk++)
            #pragma unroll
            for (int pm = 0; pm < PM; pm++) acc[c][pk][pm] = 0ull;

    const float* xb = x + (size_t)bb * CIN * 320000;

    for (int ci = 0; ci < CIN; ci++) {
        __syncthreads();
        for (int t = tid; t < WTOT; t += NT)
            wc2[t] = wd[(size_t)ci * WTOT + t];
        const float* xci = xb + (size_t)ci * 320000;
        #pragma unroll
        for (int q = 0; q < NSTG; q++) {
            if (!valq[q]) continue;
            ulonglong2 v = make_ulonglong2(0ull, 0ull);
            if (okq[q]) v = *(const ulonglong2*)(xci + srcoff[q]);
            u64* dst = &sp2[dstoff[q]];
            dst[0] = v.x;
            dst[1] = v.y;
        }
        __syncthreads();

        #pragma unroll
        for (int dij = 0; dij < 9; dij++) {
            const u64* P = sp2 + dij * 484 + k0 * 22 + m0;
            u64 w2[CO2][9];
            #pragma unroll
            for (int t = 0; t < 9; t++) {
                if (CO2 == 2) {
                    ulonglong2 wv = *(const ulonglong2*)&wc2[(dij * 9 + t) * COUT + cobase];
                    w2[0][t] = wv.x;
                    w2[CO2 - 1][t] = wv.y;
                } else {
                    w2[0][t] = wc2[(dij * 9 + t) * COUT + cobase];
                }
            }
            #pragma unroll
            for (int r = 0; r < PK + 2; r++) {
                u64 xr[PM + 2];
                #pragma unroll
                for (int h = 0; h < (PM + 2) / 2; h++) {
                    ulonglong2 v = *(const ulonglong2*)&P[r * 22 + 2 * h];
                    xr[2 * h] = v.x;
                    xr[2 * h + 1] = v.y;
                }
                #pragma unroll
                for (int dk = 0; dk < 3; dk++) {
                    int pk = r - dk;
                    if (pk < 0 || pk >= PK) continue;
                    #pragma unroll
                    for (int dm = 0; dm < 3; dm++)
                        #pragma unroll
                        for (int c = 0; c < CO2; c++)
                            #pragma unroll
                            for (int pm = 0; pm < PM; pm++)
                                fma2(acc[c][pk][pm], xr[pm + dm], w2[c][dk * 3 + dm]);
                }
            }
        }
    }

    #pragma unroll
    for (int c = 0; c < CO2; c++) {
        float* yp = y + (((size_t)(bb * COUT + cobase + c) * 400 + ij) * 400) * 2;
        #pragma unroll
        for (int pk = 0; pk < PK; pk++)
            #pragma unroll
            for (int pm = 0; pm < PM; pm++) {
                float lo, hi;
                unpack2(acc[c][pk][pm], lo, hi);
                float2 o;
                o.x = fmaxf(lo, 0.f);
                o.y = fmaxf(hi, 0.f);
                *(float2*)&yp[((k0 + pk) * 20 + m0 + pm) * 2] = o;
            }
    }
}

// ---------------- 4D conv, divisor-NT variant (conv3, unchanged R11 config) ----------------
template <int CIN, int COUT, int CO2, int PK, int PM, int NT, int MAXB>
__global__ void __launch_bounds__(NT, MAXB) conv4d_k(
        const float* __restrict__ x, const u64* __restrict__ wd,
        float* __restrict__ y) {
    constexpr int NPK = 20 / PK, NPM = 20 / PM;
    constexpr int NPATCH = NPK * NPM;
    constexpr int NSTG = 200 / NT;

    __shared__ u64 sp2[9 * 484];
    __shared__ u64 wc2[81 * COUT];

    int bij = blockIdx.x;
    int bb = bij / HW, ij = bij % HW;
    int i = ij / 20, j = ij % 20;
    int tid = threadIdx.x;
    int cobase = (tid / NPATCH) * CO2;
    int pid = tid % NPATCH;
    int k0 = (pid / NPM) * PK;
    int m0 = (pid % NPM) * PM;

    for (int t = tid; t < 9 * 484; t += NT) sp2[t] = 0ull;

    bool pok[9];
    int  po[9];
    #pragma unroll
    for (int p = 0; p < 9; p++) {
        int di = p / 3, dj = p % 3;
        int ii = i + di - 1, jj = j + dj - 1;
        pok[p] = ((unsigned)ii < 20u) && ((unsigned)jj < 20u);
        po[p]  = (ii * 20 + jj) * 800;
    }
    int  soff[NSTG];
    int  doff[NSTG];
    #pragma unroll
    for (int q = 0; q < NSTG; q++) {
        int rem2 = tid + q * NT;
        int r = rem2 / 10, c2 = (rem2 % 10) * 2;
        soff[q] = (r * 20 + c2) * 2;
        doff[q] = (r + 1) * 22 + (c2 + 1);
    }

    u64 acc[CO2][PK][PM];
    #pragma unroll
    for (int c = 0; c < CO2; c++)
        #pragma unroll
        for (int pk = 0; pk < PK; pk++)
            #pragma unroll
            for (int pm = 0; pm < PM; pm++) acc[c][pk][pm] = 0ull;

    const float* xb = x + (size_t)bb * CIN * 320000;

    for (int ci = 0; ci < CIN; ci++) {
        __syncthreads();
        for (int t = tid; t < 81 * COUT; t += NT)
            wc2[t] = wd[(size_t)ci * 81 * COUT + t];
        const float* xci = xb + (size_t)ci * 320000;
        #pragma unroll
        for (int p = 0; p < 9; p++) {
            #pragma unroll
            for (int q = 0; q < NSTG; q++) {
                ulonglong2 v = make_ulonglong2(0ull, 0ull);
                if (pok[p]) v = *(const ulonglong2*)(xci + po[p] + soff[q]);
                u64* dst = &sp2[p * 484 + doff[q]];
                dst[0] = v.x;
                dst[1] = v.y;
            }
        }
        __syncthreads();

        #pragma unroll
        for (int dij = 0; dij < 9; dij++) {
            const u64* P = sp2 + dij * 484 + k0 * 22 + m0;
            u64 w2[CO2][9];
            #pragma unroll
            for (int t = 0; t < 9; t++) {
                if (CO2 == 2) {
                    ulonglong2 wv = *(const ulonglong2*)&wc2[(dij * 9 + t) * COUT + cobase];
                    w2[0][t] = wv.x;
                    w2[CO2 - 1][t] = wv.y;
                } else {
                    w2[0][t] = wc2[(dij * 9 + t) * COUT + cobase];
                }
            }
            #pragma unroll
            for (int r = 0; r < PK + 2; r++) {
                u64 xr[PM + 2];
                #pragma unroll
                for (int h = 0; h < (PM + 2) / 2; h++) {
                    ulonglong2 v = *(const ulonglong2*)&P[r * 22 + 2 * h];
                    xr[2 * h] = v.x;
                    xr[2 * h + 1] = v.y;
                }
                #pragma unroll
                for (int dk = 0; dk < 3; dk++) {
                    int pk = r - dk;
                    if (pk < 0 || pk >= PK) continue;
                    #pragma unroll
                    for (int dm = 0; dm < 3; dm++)
                        #pragma unroll
                        for (int c = 0; c < CO2; c++)
                            #pragma unroll
                            for (int pm = 0; pm < PM; pm++)
                                fma2(acc[c][pk][pm], xr[pm + dm], w2[c][dk * 3 + dm]);
                }
            }
        }
    }

    #pragma unroll
    for (int c = 0; c < CO2; c++) {
        float* yp = y + (((size_t)(bb * COUT + cobase + c) * 400 + ij) * 400) * 2;
        #pragma unroll
        for (int pk = 0; pk < PK; pk++)
            #pragma unroll
            for (int pm = 0; pm < PM; pm++) {
                float lo, hi;
                unpack2(acc[c][pk][pm], lo, hi);
                float2 o;
                o.x = fmaxf(lo, 0.f);
                o.y = fmaxf(hi, 0.f);
                *(float2*)&yp[((k0 + pk) * 20 + m0 + pm) * 2] = o;
            }
    }
}

// ---------------- combine branches: c4[q][s] = I[q][s].x + I[s][q].y ----------------
__global__ void addt2_k(const float* __restrict__ I, float* __restrict__ o) {
    __shared__ float t1[32][33];
    __shared__ float t2[32][33];
    int b = blockIdx.z;
    const float* Ib = I + (size_t)b * HW * HW * 2;
    float* O = o + (size_t)b * HW * HW;
    int q0 = blockIdx.y * 32, s0 = blockIdx.x * 32;
    int tx = threadIdx.x, ty = threadIdx.y;
    #pragma unroll
    for (int r = 0; r < 32; r += 8) {
        int q = q0 + ty + r, s = s0 + tx;
        t1[ty + r][tx] = (q < HW && s < HW) ? Ib[((size_t)q * HW + s) * 2] : 0.f;
        int s2 = s0 + ty + r, q2 = q0 + tx;
        t2[ty + r][tx] = (s2 < HW && q2 < HW) ? Ib[((size_t)s2 * HW + q2) * 2 + 1] : 0.f;
    }
    __syncthreads();
    #pragma unroll
    for (int r = 0; r < 32; r += 8) {
        int q = q0 + ty + r, s = s0 + tx;
        if (q < HW && s < HW) O[(size_t)q * HW + s] = t1[ty + r][tx] + t2[tx][ty + r];
    }
}

// ---------------- softmax ----------------
__global__ void softmax_k(const float* __restrict__ x, float* __restrict__ y) {
    int row = blockIdx.x;
    const float* xr = x + (size_t)row * HW;
    float*       yr = y + (size_t)row * HW;
    __shared__ float sh[HW];
    __shared__ float red[4];
    int tid = threadIdx.x;
    float mx = -3.4e38f;
    for (int i = tid; i < HW; i += 128) {
        float v = xr[i] * TEMP;
        sh[i] = v;
        mx = fmaxf(mx, v);
    }
    #pragma unroll
    for (int o = 16; o; o >>= 1) mx = fmaxf(mx, __shfl_xor_sync(0xffffffffu, mx, o));
    if ((tid & 31) == 0) red[tid >> 5] = mx;
    __syncthreads();
    mx = fmaxf(fmaxf(red[0], red[1]), fmaxf(red[2], red[3]));
    float sum = 0.f;
    for (int i = tid; i < HW; i += 128) {
        float e = expf(sh[i] - mx);
        sh[i] = e;
        sum += e;
    }
    #pragma unroll
    for (int o = 16; o; o >>= 1) sum += __shfl_xor_sync(0xffffffffu, sum, o);
    __syncthreads();
    if ((tid & 31) == 0) red[tid >> 5] = sum;
    __syncthreads();
    float inv = 1.f / (red[0] + red[1] + red[2] + red[3]);
    for (int i = tid; i < HW; i += 128) yr[i] = sh[i] * inv;
}

// ---------------- attention GEMM (NT) ----------------
__global__ void attn_gemm_k(const float* __restrict__ attn, const float* __restrict__ v,
                            float* __restrict__ out) {
    int b = blockIdx.z;
    const float* A = v    + (size_t)b * CH * HW;
    const float* P = attn + (size_t)b * HW * HW;
    int c0 = blockIdx.y * 64, q0 = blockIdx.x * 64;

    __shared__ float As[16][65];
    __shared__ float Ps[16][65];
    int tid = threadIdx.x;
    int tx = tid & 15, ty = tid >> 4;
    float acc[4][4] = {};

    for (int s0 = 0; s0 < HW; s0 += 16) {
        #pragma unroll
        for (int t = tid; t < 1024; t += 256) {
            int row = t >> 4, kk = t & 15;
            int c = c0 + row, q = q0 + row;
            As[kk][row] = (c < CH) ? A[(size_t)c * HW + s0 + kk] : 0.f;
            Ps[kk][row] = (q < HW) ? P[(size_t)q * HW + s0 + kk] : 0.f;
        }
        __syncthreads();
        #pragma unroll
        for (int kk = 0; kk < 16; kk++) {
            float a[4], p[4];
            #pragma unroll
            for (int r = 0; r < 4; r++) { a[r] = As[kk][ty * 4 + r]; p[r] = Ps[kk][tx * 4 + r]; }
            #pragma unroll
            for (int r = 0; r < 4; r++)
                #pragma unroll
                for (int s = 0; s < 4; s++) acc[r][s] += a[r] * p[s];
        }
        __syncthreads();
    }
    #pragma unroll
    for (int r = 0; r < 4; r++) {
        int c = c0 + ty * 4 + r;
        if (c >= CH) continue;
        #pragma unroll
        for (int s = 0; s < 4; s++) {
            int q = q0 + tx * 4 + s;
            if (q < HW) out[((size_t)b * CH + c) * HW + q] = acc[r][s];
        }
    }
}

// ---------------- final norms + combine ----------------
__global__ void norm2_k(const float* __restrict__ fqin, const float* __restrict__ att,
                        float* __restrict__ nrm) {
    int b = blockIdx.x, z = blockIdx.y;
    const float* x = (z ? att : fqin) + (size_t)b * CH * HW + threadIdx.x;
    float s0 = 0.f, s1 = 0.f, s2 = 0.f, s3 = 0.f;
    #pragma unroll 4
    for (int c = 0; c < CH; c += 4) {
        float v0 = x[(size_t)(c + 0) * HW];
        float v1 = x[(size_t)(c + 1) * HW];
        float v2 = x[(size_t)(c + 2) * HW];
        float v3 = x[(size_t)(c + 3) * HW];
        s0 += v0 * v0; s1 += v1 * v1; s2 += v2 * v2; s3 += v3 * v3;
    }
    float s = (s0 + s1) + (s2 + s3);
    nrm[(z * BS + b) * HW + threadIdx.x] = 1.f / fmaxf(sqrtf(s), 1e-12f);
}

__global__ void combine_k(const float* __restrict__ fqin, const float* __restrict__ att,
                          const float* __restrict__ nrm, float* __restrict__ out) {
    int idx = blockIdx.x * blockDim.x + threadIdx.x;
    if (idx >= BS * CH * HW) return;
    int b = idx / (CH * HW);
    int pos = idx % HW;
    out[idx] = fqin[idx] * nrm[b * HW + pos] + att[idx] * nrm[(BS + b) * HW + pos] * 0.5f;
}

// ---------------- launch ----------------
extern "C" void kernel_launch(void* const* d_in, const int* in_sizes, int n_in,
                              void* d_out, int out_size) {
    const float* fqf = (const float*)d_in[0];
    const float* fsf = (const float*)d_in[1];
    const float* f_q = (const float*)d_in[2];
    const float* f_s = (const float*)d_in[3];
    const float* w1  = (const float*)d_in[4];
    const float* w2  = (const float*)d_in[5];
    const float* w3  = (const float*)d_in[6];
    float* out = (float*)d_out;

    float *part, *invn, *corr, *corrI, *buf1, *buf2, *c4ab, *c4, *attn, *nrm;
    int* cnt;
    u64 *wd1, *wd2, *wd3;
    cudaGetSymbolAddress((void**)&part,  g_part);
    cudaGetSymbolAddress((void**)&cnt,   g_cnt);
    cudaGetSymbolAddress((void**)&invn,  g_invn);
    cudaGetSymbolAddress((void**)&corr,  g_corr);
    cudaGetSymbolAddress((void**)&corrI, g_corrI);
    cudaGetSymbolAddress((void**)&buf1,  g_buf1I);
    cudaGetSymbolAddress((void**)&buf2,  g_buf2I);
    cudaGetSymbolAddress((void**)&c4ab,  g_c4abI);
    cudaGetSymbolAddress((void**)&c4,    g_c4);
    cudaGetSymbolAddress((void**)&attn,  g_attn);
    cudaGetSymbolAddress((void**)&nrm,   g_nrm);
    cudaGetSymbolAddress((void**)&wd1,   g_wd1);
    cudaGetSymbolAddress((void**)&wd2,   g_wd2);
    cudaGetSymbolAddress((void**)&wd3,   g_wd3);

    // 1. prep
    prep_k<<<dim3(NLB, 2, 8), 400>>>(fqf, fsf, part, cnt, invn, w1, w2, w3, wd1, wd2, wd3);

    // 2. correlation tensor
    corr_gemm_k<<<dim3(2, 4, NLB), 400>>>(fqf, fsf, invn, corr);

    // 3. branch-interleave
    transI_k<<<dim3(13, 13, NLB), dim3(32, 8)>>>(corr, corrI);

    // 4. neighborhood consensus (launch #4 = conv1 -> ncu capture)
    //    NEW: CO2=2, PK=4, PM=2, NT=250, 3 blocks/SM (750 thr/SM)
    conv4d_g_k<9, 10, 2, 4, 2, 250, 3><<<BS * HW, 250>>>(corrI, wd1, buf1);
    conv4d_g_k<10, 10, 2, 4, 2, 250, 3><<<BS * HW, 250>>>(buf1, wd2, buf2);
    conv4d_k<10, 1, 1, 2, 2, 100, 4><<<BS * HW, 100>>>(buf2, wd3, c4ab);

    // 5. combine branches
    addt2_k<<<dim3(13, 13, BS), dim3(32, 8)>>>(c4ab, c4);

    // 6. softmax + attention
    softmax_k<<<BS * HW, 128>>>(c4, attn);
    attn_gemm_k<<<dim3(7, 4, BS), 256>>>(attn, f_s, out + BS * CH * HW);

    // 7. final L2-norm combine
    norm2_k<<<dim3(BS, 2), 400>>>(f_q, out + BS * CH * HW, nrm);
    combine_k<<<(BS * CH * HW + 255) / 256, 256>>>(f_q, out + BS * CH * HW, nrm, out);
}